// round 14
// baseline (speedup 1.0000x reference)
#include <cuda_runtime.h>
#include <math.h>

#define BB    2
#define NN    8192
#define NDWN  1024
#define KNN   16
#define AD    128
#define QKVD  384
#define DIMF  256

// ---------------- packed fp32 helpers (Blackwell FFMA2) -----------------------
__device__ __forceinline__ void ffma2(unsigned long long &acc,
                                      unsigned long long a,
                                      unsigned long long w) {
    asm("fma.rn.f32x2 %0, %1, %2, %3;" : "=l"(acc) : "l"(a), "l"(w), "l"(acc));
}
__device__ __forceinline__ unsigned long long pack2(float lo, float hi) {
    unsigned long long r;
    asm("mov.b64 %0, {%1, %2};" : "=l"(r) : "f"(lo), "f"(hi));
    return r;
}
__device__ __forceinline__ void unpack2(unsigned long long v, float &lo, float &hi) {
    asm("mov.b64 {%0, %1}, %2;" : "=f"(lo), "=f"(hi) : "l"(v));
}

// ---------------- cp.async helpers --------------------------------------------
__device__ __forceinline__ void cp_async16(void* smem, const void* gmem) {
    unsigned s = (unsigned)__cvta_generic_to_shared(smem);
    asm volatile("cp.async.ca.shared.global [%0], [%1], 16;\n" :: "r"(s), "l"(gmem));
}
#define CP_ASYNC_COMMIT()   asm volatile("cp.async.commit_group;\n" ::: "memory")
#define CP_ASYNC_WAIT_ALL() asm volatile("cp.async.wait_group 0;\n" ::: "memory")

// ---------------- device scratch ---------------------------------------------
__device__ float d_qkv_l[BB*NN*QKVD];
__device__ float d_qkv_g[BB*NN*QKVD];
__device__ float d_cat  [BB*NN*2*AD];
__device__ float d_hid  [BB*NN*DIMF];
__device__ float d_kmax [BB*NDWN*AD];
__device__ float d_vmax [BB*NDWN*AD];
__device__ float d_down_xyzp[BB*NDWN*4];
__device__ float d_pos_l[(size_t)BB*NN*KNN*AD];
__device__ float d_pos_g[(size_t)BB*NN*KNN*AD];
__device__ int   d_idx_l  [BB*NN*KNN];
__device__ int   d_idx_inv[BB*NN*KNN];
__device__ int   d_down_idx[BB*NDWN];

// ---------------- KNN: FROZEN byte-for-byte from R11 --------------------------
__global__ void __launch_bounds__(256) knn_kernel(
    const float* __restrict__ qpts, int Q,
    const float* __restrict__ rpts, int R,
    int* __restrict__ out)
{
    __shared__ float4 sref[2048];           // two half-tiles of 1024 (32 KB)
    int b = blockIdx.y;
    const float* qb = qpts + (size_t)b * Q * 4;
    const float* rb = rpts + (size_t)b * R * 4;
    int qslot = threadIdx.x & 127;
    int half  = threadIdx.x >> 7;
    int qi = blockIdx.x * 128 + qslot;
    int Rh = R >> 1;

    float qx = qb[qi*4+0], qy = qb[qi*4+1], qz = qb[qi*4+2];
    float s1 = qx*qx + qy*qy + qz*qz;

    float best[KNN];
    int   bid [KNN];
#pragma unroll
    for (int t = 0; t < KNN; t++) { best[t] = 3.4e38f; bid[t] = 0; }

    for (int off = 0; off < Rh; off += 1024) {
        int cnt = min(1024, Rh - off);
        __syncthreads();
        for (int t = threadIdx.x; t < 2048; t += 256) {
            int local = t & 1023;
            int th    = t >> 10;
            if (local < cnt) {
                float4 p = *reinterpret_cast<const float4*>(rb + (size_t)(th*Rh + off + local) * 4);
                p.w = p.x*p.x + p.y*p.y + p.z*p.z;
                sref[t] = p;
            }
        }
        __syncthreads();
        const float4* sp = sref + (half << 10);
        int base = half*Rh + off;
#pragma unroll 8
        for (int t = 0; t < cnt; t++) {
            float4 p = sp[t];
            float dot = qx*p.x + qy*p.y + qz*p.z;       // FROZEN arithmetic
            float d   = s1 - 2.0f*dot + p.w;
            if (__any_sync(0xffffffffu, d < best[KNN-1])) {
                if (d < best[KNN-1]) {
                    float cd = d; int ci = base + t;
#pragma unroll
                    for (int s = 0; s < KNN; s++) {
                        if (cd < best[s]) {
                            float td = best[s]; int ti = bid[s];
                            best[s] = cd; bid[s] = ci;
                            cd = td; ci = ti;
                        }
                    }
                }
            }
        }
    }

    __syncthreads();
    float* ld = (float*)sref;
    int*   li = (int*)(ld + 4096);
#pragma unroll
    for (int j = 0; j < KNN; j++) {
        int e = qslot*32 + half*16 + j;
        ld[e] = best[j]; li[e] = bid[j];
    }
    __syncthreads();
    if (half == 0) {
        const float* dA = ld + qslot*32;
        const float* dB = dA + 16;
        const int*   xA = li + qslot*32;
        const int*   xB = xA + 16;
        int ia = 0, ib = 0;
        int* op = out + ((size_t)b * Q + qi) * KNN;
#pragma unroll
        for (int r = 0; r < KNN; r++) {
            float da = dA[ia], db = dB[ib];
            bool tb = (db < da) || (db == da && xB[ib] < xA[ia]);
            op[r] = tb ? xB[ib] : xA[ia];
            if (tb) ib++; else ia++;
        }
    }
}

// ---------------- FPS: register-resident xyz + smin, REDUX reductions ---------
// Same expressions, same i-order, same (max, min-idx) semantics -> identical
// selections. Only storage changed (smem -> regs for per-thread data).
__global__ void __launch_bounds__(1024) fps_kernel(const float* __restrict__ xyzp)
{
    extern __shared__ float sm[];
    float* sx = sm;
    float* sy = sm + NN;
    float* sz = sm + 2*NN;
    __shared__ float rv[32];
    __shared__ int   ri[32];
    __shared__ int   sel;

    int b = blockIdx.x, tid = threadIdx.x;
    const float* xb = xyzp + (size_t)b * NN * 4;

    float x0 = xb[0], y0 = xb[1], z0 = xb[2];
    float xr[8], yr[8], zr[8], dmin[8];
    float bv = -1.f; int bi = 0;
#pragma unroll
    for (int u = 0; u < 8; u++) {
        int i = tid + u*1024;
        float x = xb[i*4+0], y = xb[i*4+1], z = xb[i*4+2];
        sx[i] = x; sy[i] = y; sz[i] = z;
        xr[u] = x; yr[u] = y; zr[u] = z;
        float dx = x - x0, dy = y - y0, dz = z - z0;
        float d = dx*dx + dy*dy + dz*dz;
        dmin[u] = d;
        if (d > bv) { bv = d; bi = i; }
    }
    if (tid == 0) d_down_idx[b*NDWN] = 0;

    for (int s = 1; s < NDWN; s++) {
        {
            unsigned key  = __float_as_uint(bv);
            unsigned kmax = __reduce_max_sync(0xffffffffu, key);
            unsigned cidx = (key == kmax) ? (unsigned)bi : 0xffffffffu;
            unsigned imin = __reduce_min_sync(0xffffffffu, cidx);
            if ((tid & 31) == 0) { rv[tid >> 5] = __uint_as_float(kmax); ri[tid >> 5] = (int)imin; }
        }
        __syncthreads();
        if (tid < 32) {
            float v = rv[tid]; int ii = ri[tid];
            unsigned key  = __float_as_uint(v);
            unsigned kmax = __reduce_max_sync(0xffffffffu, key);
            unsigned cidx = (key == kmax) ? (unsigned)ii : 0xffffffffu;
            unsigned imin = __reduce_min_sync(0xffffffffu, cidx);
            if (tid == 0) { sel = (int)imin; d_down_idx[b*NDWN + s] = (int)imin; }
        }
        __syncthreads();
        int p = sel;
        float px = sx[p], py = sy[p], pz = sz[p];
        bv = -1.f; bi = 0;
#pragma unroll
        for (int u = 0; u < 8; u++) {
            int i = tid + u*1024;
            float dx = xr[u]-px, dy = yr[u]-py, dz = zr[u]-pz;
            float d  = dx*dx + dy*dy + dz*dz;
            float v  = fminf(dmin[u], d);
            dmin[u]  = v;
            if (v > bv) { bv = v; bi = i; }
        }
    }
}

__global__ void gather_down_kernel(const float* __restrict__ xyzp)
{
    int t = blockIdx.x * blockDim.x + threadIdx.x;
    if (t < BB*NDWN) {
        int b = t / NDWN;
        int id = d_down_idx[t];
        const float* src = xyzp + ((size_t)b * NN + id) * 4;
        float* dst = d_down_xyzp + (size_t)t * 4;
        dst[0]=src[0]; dst[1]=src[1]; dst[2]=src[2]; dst[3]=src[3];
    }
}

// ---------------- shared GEMM inner-compute (FROZEN from R12) -----------------
__device__ __forceinline__ void gemm_tile_compute(
    const float (*As)[132], const float (*Ws)[128],
    int tm, int tn, unsigned long long (&acc2)[8][4])
{
#pragma unroll
    for (int k = 0; k < 16; k++) {
        unsigned long long w2[4];
        float4 wv0 = *reinterpret_cast<const float4*>(&Ws[k][tn]);
        float4 wv1 = *reinterpret_cast<const float4*>(&Ws[k][tn+4]);
        w2[0] = pack2(wv0.x, wv0.y); w2[1] = pack2(wv0.z, wv0.w);
        w2[2] = pack2(wv1.x, wv1.y); w2[3] = pack2(wv1.z, wv1.w);
        float4 av0 = *reinterpret_cast<const float4*>(&As[k][tm]);
        float4 av1 = *reinterpret_cast<const float4*>(&As[k][tm+4]);
        unsigned long long a2[8];
        a2[0]=pack2(av0.x,av0.x); a2[1]=pack2(av0.y,av0.y);
        a2[2]=pack2(av0.z,av0.z); a2[3]=pack2(av0.w,av0.w);
        a2[4]=pack2(av1.x,av1.x); a2[5]=pack2(av1.y,av1.y);
        a2[6]=pack2(av1.z,av1.z); a2[7]=pack2(av1.w,av1.w);
#pragma unroll
        for (int i = 0; i < 8; i++)
#pragma unroll
            for (int jp = 0; jp < 4; jp++)
                ffma2(acc2[i][jp], a2[i], w2[jp]);
    }
}

// ---------------- generic fp32 tiled GEMM (FROZEN from R13) -------------------
template<bool RELU>
__global__ void __launch_bounds__(256) gemm_kernel(
    const float* __restrict__ A, const float* __restrict__ W,
    const float* __restrict__ bias, float* __restrict__ C,
    int M, int K, int Nc)
{
    __shared__ float As[2][16][132];
    __shared__ float Ws[2][16][128];
    int bm = blockIdx.y * 128, bn = blockIdx.x * 128;
    int tid = threadIdx.x;
    int tm = (tid / 16) * 8, tn = (tid % 16) * 8;
    int m0 = tid >> 2, k4 = tid & 3;
    int wk = tid >> 5, wn = tid & 31;

    unsigned long long acc2[8][4];
#pragma unroll
    for (int i = 0; i < 8; i++)
#pragma unroll
        for (int jp = 0; jp < 4; jp++) acc2[i][jp] = 0ull;

    {
        float4 v0 = *reinterpret_cast<const float4*>(A + (size_t)(bm+m0)*K + k4*4);
        float4 v1 = *reinterpret_cast<const float4*>(A + (size_t)(bm+m0+64)*K + k4*4);
        As[0][k4*4+0][m0] = v0.x; As[0][k4*4+1][m0] = v0.y;
        As[0][k4*4+2][m0] = v0.z; As[0][k4*4+3][m0] = v0.w;
        As[0][k4*4+0][m0+64] = v1.x; As[0][k4*4+1][m0+64] = v1.y;
        As[0][k4*4+2][m0+64] = v1.z; As[0][k4*4+3][m0+64] = v1.w;
        cp_async16(&Ws[0][wk][wn*4],   W + (size_t)wk*Nc + bn + wn*4);
        cp_async16(&Ws[0][wk+8][wn*4], W + (size_t)(wk+8)*Nc + bn + wn*4);
        CP_ASYNC_COMMIT(); CP_ASYNC_WAIT_ALL();
    }
    __syncthreads();

    int nsteps = K >> 4;
    for (int s = 0; s < nsteps; s++) {
        int cur = s & 1, nxt = cur ^ 1;
        bool pre = (s + 1 < nsteps);
        float4 p0, p1;
        if (pre) {
            int k0n = (s + 1) << 4;
            p0 = *reinterpret_cast<const float4*>(A + (size_t)(bm+m0)*K + k0n + k4*4);
            p1 = *reinterpret_cast<const float4*>(A + (size_t)(bm+m0+64)*K + k0n + k4*4);
            cp_async16(&Ws[nxt][wk][wn*4],   W + (size_t)(k0n+wk)*Nc + bn + wn*4);
            cp_async16(&Ws[nxt][wk+8][wn*4], W + (size_t)(k0n+wk+8)*Nc + bn + wn*4);
            CP_ASYNC_COMMIT();
        }
        gemm_tile_compute(As[cur], Ws[cur], tm, tn, acc2);
        if (pre) {
            As[nxt][k4*4+0][m0] = p0.x; As[nxt][k4*4+1][m0] = p0.y;
            As[nxt][k4*4+2][m0] = p0.z; As[nxt][k4*4+3][m0] = p0.w;
            As[nxt][k4*4+0][m0+64] = p1.x; As[nxt][k4*4+1][m0+64] = p1.y;
            As[nxt][k4*4+2][m0+64] = p1.z; As[nxt][k4*4+3][m0+64] = p1.w;
            CP_ASYNC_WAIT_ALL();
        }
        __syncthreads();
    }
#pragma unroll
    for (int i = 0; i < 8; i++)
#pragma unroll
        for (int jp = 0; jp < 4; jp++) {
            float lo, hi;
            unpack2(acc2[i][jp], lo, hi);
            float v0 = lo + bias[bn+tn+2*jp];
            float v1 = hi + bias[bn+tn+2*jp+1];
            if (RELU) { v0 = fmaxf(v0, 0.f); v1 = fmaxf(v1, 0.f); }
            float2 st; st.x = v0; st.y = v1;
            *reinterpret_cast<float2*>(&C[(size_t)(bm+tm+i)*Nc + bn+tn+2*jp]) = st;
        }
}

// ---------------- fused dual-QKV GEMM (FROZEN from R13) -----------------------
__global__ void __launch_bounds__(256) gemm_qkv2_kernel(
    const float* __restrict__ A,
    const float* __restrict__ Wl, const float* __restrict__ bl,
    const float* __restrict__ Wg, const float* __restrict__ bg,
    float* __restrict__ Cl, float* __restrict__ Cg,
    int M, int K)
{
    __shared__ float As[2][16][132];
    __shared__ float Ws[2][16][128];
    int bm = blockIdx.y * 128;
    int bnRaw = blockIdx.x * 128;
    bool isL = bnRaw < QKVD;
    const float* W    = isL ? Wl : Wg;
    const float* bias = isL ? bl : bg;
    float*       C    = isL ? Cl : Cg;
    int bn = isL ? bnRaw : bnRaw - QKVD;
    const int Nc = QKVD;
    int tid = threadIdx.x;
    int tm = (tid / 16) * 8, tn = (tid % 16) * 8;
    int m0 = tid >> 2, k4 = tid & 3;
    int wk = tid >> 5, wn = tid & 31;

    unsigned long long acc2[8][4];
#pragma unroll
    for (int i = 0; i < 8; i++)
#pragma unroll
        for (int jp = 0; jp < 4; jp++) acc2[i][jp] = 0ull;

    {
        float4 v0 = *reinterpret_cast<const float4*>(A + (size_t)(bm+m0)*K + k4*4);
        float4 v1 = *reinterpret_cast<const float4*>(A + (size_t)(bm+m0+64)*K + k4*4);
        As[0][k4*4+0][m0] = v0.x; As[0][k4*4+1][m0] = v0.y;
        As[0][k4*4+2][m0] = v0.z; As[0][k4*4+3][m0] = v0.w;
        As[0][k4*4+0][m0+64] = v1.x; As[0][k4*4+1][m0+64] = v1.y;
        As[0][k4*4+2][m0+64] = v1.z; As[0][k4*4+3][m0+64] = v1.w;
        cp_async16(&Ws[0][wk][wn*4],   W + (size_t)wk*Nc + bn + wn*4);
        cp_async16(&Ws[0][wk+8][wn*4], W + (size_t)(wk+8)*Nc + bn + wn*4);
        CP_ASYNC_COMMIT(); CP_ASYNC_WAIT_ALL();
    }
    __syncthreads();

    int nsteps = K >> 4;
    for (int s = 0; s < nsteps; s++) {
        int cur = s & 1, nxt = cur ^ 1;
        bool pre = (s + 1 < nsteps);
        float4 p0, p1;
        if (pre) {
            int k0n = (s + 1) << 4;
            p0 = *reinterpret_cast<const float4*>(A + (size_t)(bm+m0)*K + k0n + k4*4);
            p1 = *reinterpret_cast<const float4*>(A + (size_t)(bm+m0+64)*K + k0n + k4*4);
            cp_async16(&Ws[nxt][wk][wn*4],   W + (size_t)(k0n+wk)*Nc + bn + wn*4);
            cp_async16(&Ws[nxt][wk+8][wn*4], W + (size_t)(k0n+wk+8)*Nc + bn + wn*4);
            CP_ASYNC_COMMIT();
        }
        gemm_tile_compute(As[cur], Ws[cur], tm, tn, acc2);
        if (pre) {
            As[nxt][k4*4+0][m0] = p0.x; As[nxt][k4*4+1][m0] = p0.y;
            As[nxt][k4*4+2][m0] = p0.z; As[nxt][k4*4+3][m0] = p0.w;
            As[nxt][k4*4+0][m0+64] = p1.x; As[nxt][k4*4+1][m0+64] = p1.y;
            As[nxt][k4*4+2][m0+64] = p1.z; As[nxt][k4*4+3][m0+64] = p1.w;
            CP_ASYNC_WAIT_ALL();
        }
        __syncthreads();
    }
#pragma unroll
    for (int i = 0; i < 8; i++)
#pragma unroll
        for (int jp = 0; jp < 4; jp++) {
            float lo, hi;
            unpack2(acc2[i][jp], lo, hi);
            float2 st;
            st.x = lo + bias[bn+tn+2*jp];
            st.y = hi + bias[bn+tn+2*jp+1];
            *reinterpret_cast<float2*>(&C[(size_t)(bm+tm+i)*Nc + bn+tn+2*jp]) = st;
        }
}

// ---------------- split projection-1 GEMM (FROZEN from R13) -------------------
template<int PHASE>
__global__ void __launch_bounds__(256) gemm_proj1_kernel(
    const float* __restrict__ A, int lda,
    const float* __restrict__ W,
    const float* __restrict__ bias,
    float* __restrict__ C,
    int M, int K, int Nc)
{
    __shared__ float As[2][16][132];
    __shared__ float Ws[2][16][128];
    int bm = blockIdx.y * 128, bn = blockIdx.x * 128;
    int tid = threadIdx.x;
    int tm = (tid / 16) * 8, tn = (tid % 16) * 8;
    int m0 = tid >> 2, k4 = tid & 3;
    int wk = tid >> 5, wn = tid & 31;

    unsigned long long acc2[8][4];
#pragma unroll
    for (int i = 0; i < 8; i++)
#pragma unroll
        for (int jp = 0; jp < 4; jp++) acc2[i][jp] = 0ull;

    {
        float4 v0 = *reinterpret_cast<const float4*>(A + (size_t)(bm+m0)*lda + k4*4);
        float4 v1 = *reinterpret_cast<const float4*>(A + (size_t)(bm+m0+64)*lda + k4*4);
        As[0][k4*4+0][m0] = v0.x; As[0][k4*4+1][m0] = v0.y;
        As[0][k4*4+2][m0] = v0.z; As[0][k4*4+3][m0] = v0.w;
        As[0][k4*4+0][m0+64] = v1.x; As[0][k4*4+1][m0+64] = v1.y;
        As[0][k4*4+2][m0+64] = v1.z; As[0][k4*4+3][m0+64] = v1.w;
        cp_async16(&Ws[0][wk][wn*4],   W + (size_t)wk*Nc + bn + wn*4);
        cp_async16(&Ws[0][wk+8][wn*4], W + (size_t)(wk+8)*Nc + bn + wn*4);
        CP_ASYNC_COMMIT(); CP_ASYNC_WAIT_ALL();
    }
    __syncthreads();

    int nsteps = K >> 4;
    for (int s = 0; s < nsteps; s++) {
        int cur = s & 1, nxt = cur ^ 1;
        bool pre = (s + 1 < nsteps);
        float4 p0, p1;
        if (pre) {
            int k0n = (s + 1) << 4;
            p0 = *reinterpret_cast<const float4*>(A + (size_t)(bm+m0)*lda + k0n + k4*4);
            p1 = *reinterpret_cast<const float4*>(A + (size_t)(bm+m0+64)*lda + k0n + k4*4);
            cp_async16(&Ws[nxt][wk][wn*4],   W + (size_t)(k0n+wk)*Nc + bn + wn*4);
            cp_async16(&Ws[nxt][wk+8][wn*4], W + (size_t)(k0n+wk+8)*Nc + bn + wn*4);
            CP_ASYNC_COMMIT();
        }
        gemm_tile_compute(As[cur], Ws[cur], tm, tn, acc2);
        if (pre) {
            As[nxt][k4*4+0][m0] = p0.x; As[nxt][k4*4+1][m0] = p0.y;
            As[nxt][k4*4+2][m0] = p0.z; As[nxt][k4*4+3][m0] = p0.w;
            As[nxt][k4*4+0][m0+64] = p1.x; As[nxt][k4*4+1][m0+64] = p1.y;
            As[nxt][k4*4+2][m0+64] = p1.z; As[nxt][k4*4+3][m0+64] = p1.w;
            CP_ASYNC_WAIT_ALL();
        }
        __syncthreads();
    }
#pragma unroll
    for (int i = 0; i < 8; i++)
#pragma unroll
        for (int jp = 0; jp < 4; jp++) {
            float lo, hi;
            unpack2(acc2[i][jp], lo, hi);
            float* cp = &C[(size_t)(bm+tm+i)*Nc + bn+tn+2*jp];
            if (PHASE == 0) {
                float2 st;
                st.x = lo + bias[bn+tn+2*jp];
                st.y = hi + bias[bn+tn+2*jp+1];
                *reinterpret_cast<float2*>(cp) = st;
            } else {
                float2 prev = *reinterpret_cast<const float2*>(cp);
                float2 st;
                st.x = fmaxf(prev.x + lo, 0.f);
                st.y = fmaxf(prev.y + hi, 0.f);
                *reinterpret_cast<float2*>(cp) = st;
            }
        }
}

// ---------------- PE GEMM (FROZEN from R13) -----------------------------------
__global__ void __launch_bounds__(256) gemm_pe_kernel(
    const float* __restrict__ xyzp,
    const float* __restrict__ nbr, int nbr_rows,
    const int* __restrict__ nidx,
    const float* __restrict__ w1, const float* __restrict__ b1,
    const float* __restrict__ w2, const float* __restrict__ b2,
    float* __restrict__ pos)
{
    __shared__ float As[2][16][132];
    __shared__ float Ws[2][16][128];
    __shared__ float xd[128][5];
    __shared__ float w1s[4][128];
    __shared__ float b1s[128];

    int bm = blockIdx.x * 128;
    int tid = threadIdx.x;
    int wk = tid >> 5, wn = tid & 31;

    for (int t = tid; t < 512; t += 256) w1s[t >> 7][t & 127] = w1[t];
    if (tid < 128) b1s[tid] = b1[tid];
    if (tid < 128) {
        int r  = bm + tid;
        int pi = r >> 4;
        int j  = r & 15;
        int b  = pi / NN;
        int id = nidx[(size_t)pi*KNN + j];
        const float* qp = xyzp + (size_t)pi * 4;
        const float* np = nbr + ((size_t)b * nbr_rows + id) * 4;
        xd[tid][0] = qp[0]-np[0]; xd[tid][1] = qp[1]-np[1];
        xd[tid][2] = qp[2]-np[2]; xd[tid][3] = qp[3]-np[3];
    }
    __syncthreads();

    int tm = (tid / 16) * 8, tn = (tid % 16) * 8;
    unsigned long long acc2[8][4];
#pragma unroll
    for (int i = 0; i < 8; i++)
#pragma unroll
        for (int jp = 0; jp < 4; jp++) acc2[i][jp] = 0ull;

#pragma unroll
    for (int t = tid; t < 2048; t += 256) {
        int m = t & 127, k = t >> 7;
        int kk = k;
        float hv = b1s[kk] + xd[m][0]*w1s[0][kk] + xd[m][1]*w1s[1][kk]
                           + xd[m][2]*w1s[2][kk] + xd[m][3]*w1s[3][kk];
        As[0][k][m] = fmaxf(hv, 0.f);
    }
    cp_async16(&Ws[0][wk][wn*4],   w2 + (size_t)wk*128 + wn*4);
    cp_async16(&Ws[0][wk+8][wn*4], w2 + (size_t)(wk+8)*128 + wn*4);
    CP_ASYNC_COMMIT(); CP_ASYNC_WAIT_ALL();
    __syncthreads();

    for (int s = 0; s < 8; s++) {
        int cur = s & 1, nxt = cur ^ 1;
        bool pre = (s + 1 < 8);
        if (pre) {
            int k0n = (s + 1) << 4;
            cp_async16(&Ws[nxt][wk][wn*4],   w2 + (size_t)(k0n+wk)*128 + wn*4);
            cp_async16(&Ws[nxt][wk+8][wn*4], w2 + (size_t)(k0n+wk+8)*128 + wn*4);
            CP_ASYNC_COMMIT();
#pragma unroll
            for (int t = tid; t < 2048; t += 256) {
                int m = t & 127, k = t >> 7;
                int kk = k0n + k;
                float hv = b1s[kk] + xd[m][0]*w1s[0][kk] + xd[m][1]*w1s[1][kk]
                                   + xd[m][2]*w1s[2][kk] + xd[m][3]*w1s[3][kk];
                As[nxt][k][m] = fmaxf(hv, 0.f);
            }
        }
        gemm_tile_compute(As[cur], Ws[cur], tm, tn, acc2);
        if (pre) CP_ASYNC_WAIT_ALL();
        __syncthreads();
    }
#pragma unroll
    for (int i = 0; i < 8; i++)
#pragma unroll
        for (int jp = 0; jp < 4; jp++) {
            float lo, hi;
            unpack2(acc2[i][jp], lo, hi);
            float2 st;
            st.x = lo + b2[tn+2*jp];
            st.y = hi + b2[tn+2*jp+1];
            *reinterpret_cast<float2*>(&pos[(size_t)(bm+tm+i)*128 + tn+2*jp]) = st;
        }
}

// ---------------- kvmax (FROZEN) ----------------------------------------------
__global__ void __launch_bounds__(128) kvmax_kernel()
{
    int b = blockIdx.y, r = blockIdx.x, c = threadIdx.x;
    int src = d_down_idx[b*NDWN + r];
    const int* pidx = d_idx_l + ((size_t)b*NN + src)*KNN;
    float km = -3.4e38f, vm = -3.4e38f;
#pragma unroll
    for (int j = 0; j < KNN; j++) {
        int id = pidx[j];
        const float* row = d_qkv_g + ((size_t)b*NN + id)*QKVD;
        km = fmaxf(km, row[AD   + c]);
        vm = fmaxf(vm, row[2*AD + c]);
    }
    d_kmax[((size_t)b*NDWN + r)*AD + c] = km;
    d_vmax[((size_t)b*NDWN + r)*AD + c] = vm;
}

// ---------------- attention: warp-per-point, barrier-free ---------------------
// Lane handles channels {lane, lane+32, lane+64, lane+96}. Stats use the
// identical v0+v1+v2+v3 + shfl_xor butterfly (sum in all lanes); softmax runs
// j=0..15 in the frozen order per channel. All expressions verbatim.
__global__ void __launch_bounds__(256) attn_kernel(
    const int*  __restrict__ nidx,
    const float* __restrict__ qsrc,  int qstride,
    const float* __restrict__ kbase, const float* __restrict__ vbase,
    int kv_stride, int kv_rows,
    const float* __restrict__ pos,
    const float* __restrict__ fg,  const float* __restrict__ fb,
    float* __restrict__ out, int out_coloff, int base_pt)
{
    int warp = threadIdx.x >> 5, lane = threadIdx.x & 31;
    int pt = base_pt + blockIdx.x * 8 + warp;       // flattened b*NN + i
    int b  = pt / NN;
    size_t bi = (size_t)pt;

    int ids[KNN];
#pragma unroll
    for (int j = 0; j < KNN; j++) ids[j] = nidx[bi*KNN + j];

    const float* prow = pos + bi * (KNN*128);
    int c0 = lane, c1 = lane+32, c2 = lane+64, c3 = lane+96;
    float q0 = qsrc[bi*qstride + c0], q1 = qsrc[bi*qstride + c1];
    float q2 = qsrc[bi*qstride + c2], q3 = qsrc[bi*qstride + c3];

    float m_s[KNN], i_s[KNN];
#pragma unroll
    for (int j = 0; j < KNN; j++) {
        size_t kr = ((size_t)b*kv_rows + ids[j]) * kv_stride;
        float v0 = q0 - kbase[kr+c0] + prow[j*128+c0];
        float v1 = q1 - kbase[kr+c1] + prow[j*128+c1];
        float v2 = q2 - kbase[kr+c2] + prow[j*128+c2];
        float v3 = q3 - kbase[kr+c3] + prow[j*128+c3];
        float s  = v0+v1+v2+v3;
        float ss = v0*v0+v1*v1+v2*v2+v3*v3;
#pragma unroll
        for (int off = 16; off; off >>= 1) {
            s  += __shfl_xor_sync(0xffffffffu, s,  off);
            ss += __shfl_xor_sync(0xffffffffu, ss, off);
        }
        float m   = s * (1.f/128.f);
        float var = ss * (1.f/128.f) - m*m;
        if (var < 0.f) var = 0.f;
        m_s[j] = m;
        i_s[j] = 1.f / sqrtf(var + 1e-5f);
    }

    const float inv_scale = 0.08838834764831845f;   // 1/sqrt(128)
#pragma unroll
    for (int q = 0; q < 4; q++) {
        int c = lane + 32*q;
        float qv = qsrc[bi*qstride + c];
        float gr = fg[c], br = fb[c];
        float a[KNN], mx = -3.4e38f;
#pragma unroll
        for (int j = 0; j < KNN; j++) {
            size_t kr = ((size_t)b*kv_rows + ids[j]) * kv_stride;
            float pv = prow[j*128 + c];
            float tr = qv - kbase[kr + c] + pv;
            a[j] = ((tr - m_s[j]) * i_s[j] * gr + br) * inv_scale;
            mx = fmaxf(mx, a[j]);
        }
        float se = 0.f, ov = 0.f;
#pragma unroll
        for (int j = 0; j < KNN; j++) {
            float e = expf(a[j] - mx);
            se += e;
            size_t kr = ((size_t)b*kv_rows + ids[j]) * kv_stride;
            float pv = prow[j*128 + c];
            float vp = vbase[kr + c] + pv;
            ov += e * vp;
        }
        out[bi*(2*AD) + out_coloff + c] = ov / se;
    }
}

// ---------------- launcher ----------------------------------------------------
extern "C" void kernel_launch(void* const* d_in, const int* in_sizes, int n_in,
                              void* d_out, int out_size)
{
    const float* xyzp     = (const float*)d_in[0];
    const float* features = (const float*)d_in[1];
    const float* l_qkv_w  = (const float*)d_in[2];
    const float* l_qkv_b  = (const float*)d_in[3];
    const float* l_pe_w1  = (const float*)d_in[4];
    const float* l_pe_b1  = (const float*)d_in[5];
    const float* l_pe_w2  = (const float*)d_in[6];
    const float* l_pe_b2  = (const float*)d_in[7];
    const float* l_fc_g   = (const float*)d_in[8];
    const float* l_fc_b   = (const float*)d_in[9];
    const float* g_qkv_w  = (const float*)d_in[10];
    const float* g_qkv_b  = (const float*)d_in[11];
    const float* g_pe_w1  = (const float*)d_in[12];
    const float* g_pe_b1  = (const float*)d_in[13];
    const float* g_pe_w2  = (const float*)d_in[14];
    const float* g_pe_b2  = (const float*)d_in[15];
    const float* g_fc_g   = (const float*)d_in[16];
    const float* g_fc_b   = (const float*)d_in[17];
    const float* proj_w1  = (const float*)d_in[18];
    const float* proj_b1  = (const float*)d_in[19];
    const float* proj_w2  = (const float*)d_in[20];
    const float* proj_b2  = (const float*)d_in[21];
    float* out = (float*)d_out;

    float *qkv_l, *qkv_g, *cat_p, *hid_p, *kmax_p, *vmax_p, *dxyzp_p, *posl_p, *posg_p;
    int *idx_l, *idx_inv;
    cudaGetSymbolAddress((void**)&qkv_l,   d_qkv_l);
    cudaGetSymbolAddress((void**)&qkv_g,   d_qkv_g);
    cudaGetSymbolAddress((void**)&cat_p,   d_cat);
    cudaGetSymbolAddress((void**)&hid_p,   d_hid);
    cudaGetSymbolAddress((void**)&kmax_p,  d_kmax);
    cudaGetSymbolAddress((void**)&vmax_p,  d_vmax);
    cudaGetSymbolAddress((void**)&dxyzp_p, d_down_xyzp);
    cudaGetSymbolAddress((void**)&posl_p,  d_pos_l);
    cudaGetSymbolAddress((void**)&posg_p,  d_pos_g);
    cudaGetSymbolAddress((void**)&idx_l,   d_idx_l);
    cudaGetSymbolAddress((void**)&idx_inv, d_idx_inv);

    const int FPS_SMEM = 3 * NN * (int)sizeof(float);   // xyz only; smin in regs
    cudaFuncSetAttribute(fps_kernel, cudaFuncAttributeMaxDynamicSharedMemorySize, FPS_SMEM);

    static cudaStream_t sA = 0, sB = 0, sC = 0;
    static cudaEvent_t evRoot, evDown, evKNN, evQKV, evPl, evB, evC0, evC1;
    static bool inited = false;
    if (!inited) {
        int leastP = 0, greatestP = 0;
        cudaDeviceGetStreamPriorityRange(&leastP, &greatestP);
        cudaStreamCreateWithPriority(&sA, cudaStreamNonBlocking, leastP);
        cudaStreamCreateWithPriority(&sB, cudaStreamNonBlocking, greatestP);
        cudaStreamCreateWithPriority(&sC, cudaStreamNonBlocking, greatestP);
        cudaEventCreateWithFlags(&evRoot, cudaEventDisableTiming);
        cudaEventCreateWithFlags(&evDown, cudaEventDisableTiming);
        cudaEventCreateWithFlags(&evKNN,  cudaEventDisableTiming);
        cudaEventCreateWithFlags(&evQKV,  cudaEventDisableTiming);
        cudaEventCreateWithFlags(&evPl,   cudaEventDisableTiming);
        cudaEventCreateWithFlags(&evB,    cudaEventDisableTiming);
        cudaEventCreateWithFlags(&evC0,   cudaEventDisableTiming);
        cudaEventCreateWithFlags(&evC1,   cudaEventDisableTiming);
        inited = true;
    }

    const int M = BB * NN;
    const int PE_BLOCKS = (BB*NN*KNN) / 128;   // 2048

    cudaEventRecord(evRoot, 0);
    cudaStreamWaitEvent(sA, evRoot, 0);
    cudaStreamWaitEvent(sB, evRoot, 0);

    // sA: self-KNN (split) -> PE-local
    knn_kernel<<<dim3(NN/128, BB), 256, 0, sA>>>(xyzp, NN, xyzp, NN, idx_l);
    cudaEventRecord(evKNN, sA);
    gemm_pe_kernel<<<PE_BLOCKS, 256, 0, sA>>>(xyzp, xyzp, NN, idx_l,
                                              l_pe_w1, l_pe_b1, l_pe_w2, l_pe_b2, posl_p);

    // sB: FPS -> gather (fork sC after down points ready)
    fps_kernel<<<BB, 1024, FPS_SMEM, sB>>>(xyzp);
    gather_down_kernel<<<(BB*NDWN + 255)/256, 256, 0, sB>>>(xyzp);
    cudaEventRecord(evDown, sB);
    cudaStreamWaitEvent(sC, evDown, 0);

    // sC: inv-KNN (split) -> PE-global
    knn_kernel<<<dim3(NN/128, BB), 256, 0, sC>>>(xyzp, NN, dxyzp_p, NDWN, idx_inv);
    gemm_pe_kernel<<<PE_BLOCKS, 256, 0, sC>>>(xyzp, dxyzp_p, NDWN, idx_inv,
                                              g_pe_w1, g_pe_b1, g_pe_w2, g_pe_b2, posg_p);

    // default: fused dual-QKV GEMM
    gemm_qkv2_kernel<<<dim3(2*QKVD/128, M/128), 256>>>(features,
                                                       l_qkv_w, l_qkv_b,
                                                       g_qkv_w, g_qkv_b,
                                                       qkv_l, qkv_g, M, DIMF);
    cudaEventRecord(evQKV, 0);

    // sA: local attention (both batches), then proj1 local half (full M)
    cudaStreamWaitEvent(sA, evQKV, 0);
    attn_kernel<<<M/8, 256, 0, sA>>>(idx_l, qkv_l, QKVD,
                                     qkv_l + AD, qkv_l + 2*AD, QKVD, NN,
                                     posl_p, l_fc_g, l_fc_b, cat_p, 0, 0);
    gemm_proj1_kernel<0><<<dim3(DIMF/128, M/128), 256, 0, sA>>>(
        cat_p, 2*AD, proj_w1, proj_b1, hid_p, M, AD, DIMF);
    cudaEventRecord(evPl, sA);

    // sB: kvmax
    cudaStreamWaitEvent(sB, evKNN, 0);
    cudaStreamWaitEvent(sB, evQKV, 0);
    kvmax_kernel<<<dim3(NDWN, BB), 128, 0, sB>>>();
    cudaEventRecord(evB, sB);

    // sC: global attention split by batch (pipeline the tail)
    cudaStreamWaitEvent(sC, evB, 0);
    attn_kernel<<<NN/8, 256, 0, sC>>>(idx_inv, qkv_g, QKVD,
                                      kmax_p, vmax_p, AD, NDWN,
                                      posg_p, g_fc_g, g_fc_b, cat_p, AD, 0);
    cudaEventRecord(evC0, sC);
    attn_kernel<<<NN/8, 256, 0, sC>>>(idx_inv, qkv_g, QKVD,
                                      kmax_p, vmax_p, AD, NDWN,
                                      posg_p, g_fc_g, g_fc_b, cat_p, AD, NN);
    cudaEventRecord(evC1, sC);

    // default tail: batch-0 proj while batch-1 attn-g runs
    cudaStreamWaitEvent(0, evPl, 0);
    cudaStreamWaitEvent(0, evC0, 0);
    gemm_proj1_kernel<1><<<dim3(DIMF/128, NN/128), 256>>>(
        cat_p + AD, 2*AD, proj_w1 + (size_t)AD*DIMF, proj_b1, hid_p, NN, AD, DIMF);
    gemm_kernel<false><<<dim3(DIMF/128, NN/128), 256>>>(
        hid_p, proj_w2, proj_b2, out, NN, DIMF, DIMF);
    cudaStreamWaitEvent(0, evC1, 0);
    gemm_proj1_kernel<1><<<dim3(DIMF/128, NN/128), 256>>>(
        cat_p + (size_t)NN*2*AD + AD, 2*AD, proj_w1 + (size_t)AD*DIMF, proj_b1,
        hid_p + (size_t)NN*DIMF, NN, AD, DIMF);
    gemm_kernel<false><<<dim3(DIMF/128, NN/128), 256>>>(
        hid_p + (size_t)NN*DIMF, proj_w2, proj_b2, out + (size_t)NN*DIMF, NN, DIMF, DIMF);

    (void)in_sizes; (void)n_in; (void)out_size;
}

// round 15
// speedup vs baseline: 1.0577x; 1.0577x over previous
#include <cuda_runtime.h>
#include <math.h>

#define BB    2
#define NN    8192
#define NDWN  1024
#define KNN   16
#define AD    128
#define QKVD  384
#define DIMF  256
#define PPB   8

// ---------------- packed fp32 helpers (Blackwell FFMA2) -----------------------
__device__ __forceinline__ void ffma2(unsigned long long &acc,
                                      unsigned long long a,
                                      unsigned long long w) {
    asm("fma.rn.f32x2 %0, %1, %2, %3;" : "=l"(acc) : "l"(a), "l"(w), "l"(acc));
}
__device__ __forceinline__ unsigned long long pack2(float lo, float hi) {
    unsigned long long r;
    asm("mov.b64 %0, {%1, %2};" : "=l"(r) : "f"(lo), "f"(hi));
    return r;
}
__device__ __forceinline__ void unpack2(unsigned long long v, float &lo, float &hi) {
    asm("mov.b64 {%0, %1}, %2;" : "=f"(lo), "=f"(hi) : "l"(v));
}

// ---------------- cp.async helpers --------------------------------------------
__device__ __forceinline__ void cp_async16(void* smem, const void* gmem) {
    unsigned s = (unsigned)__cvta_generic_to_shared(smem);
    asm volatile("cp.async.ca.shared.global [%0], [%1], 16;\n" :: "r"(s), "l"(gmem));
}
#define CP_ASYNC_COMMIT()   asm volatile("cp.async.commit_group;\n" ::: "memory")
#define CP_ASYNC_WAIT_ALL() asm volatile("cp.async.wait_group 0;\n" ::: "memory")

// ---------------- device scratch ---------------------------------------------
__device__ float d_qkv_l[BB*NN*QKVD];
__device__ float d_qkv_g[BB*NN*QKVD];
__device__ float d_cat  [BB*NN*2*AD];
__device__ float d_hid  [BB*NN*DIMF];
__device__ float d_kmax [BB*NDWN*AD];
__device__ float d_vmax [BB*NDWN*AD];
__device__ float d_down_xyzp[BB*NDWN*4];
__device__ float d_pos_l[(size_t)BB*NN*KNN*AD];
__device__ float d_pos_g[(size_t)BB*NN*KNN*AD];
__device__ int   d_idx_l  [BB*NN*KNN];
__device__ int   d_idx_inv[BB*NN*KNN];
__device__ int   d_down_idx[BB*NDWN];

// ---------------- KNN: FROZEN byte-for-byte from R11 --------------------------
__global__ void __launch_bounds__(256) knn_kernel(
    const float* __restrict__ qpts, int Q,
    const float* __restrict__ rpts, int R,
    int* __restrict__ out)
{
    __shared__ float4 sref[2048];           // two half-tiles of 1024 (32 KB)
    int b = blockIdx.y;
    const float* qb = qpts + (size_t)b * Q * 4;
    const float* rb = rpts + (size_t)b * R * 4;
    int qslot = threadIdx.x & 127;
    int half  = threadIdx.x >> 7;
    int qi = blockIdx.x * 128 + qslot;
    int Rh = R >> 1;

    float qx = qb[qi*4+0], qy = qb[qi*4+1], qz = qb[qi*4+2];
    float s1 = qx*qx + qy*qy + qz*qz;

    float best[KNN];
    int   bid [KNN];
#pragma unroll
    for (int t = 0; t < KNN; t++) { best[t] = 3.4e38f; bid[t] = 0; }

    for (int off = 0; off < Rh; off += 1024) {
        int cnt = min(1024, Rh - off);
        __syncthreads();
        for (int t = threadIdx.x; t < 2048; t += 256) {
            int local = t & 1023;
            int th    = t >> 10;
            if (local < cnt) {
                float4 p = *reinterpret_cast<const float4*>(rb + (size_t)(th*Rh + off + local) * 4);
                p.w = p.x*p.x + p.y*p.y + p.z*p.z;
                sref[t] = p;
            }
        }
        __syncthreads();
        const float4* sp = sref + (half << 10);
        int base = half*Rh + off;
#pragma unroll 8
        for (int t = 0; t < cnt; t++) {
            float4 p = sp[t];
            float dot = qx*p.x + qy*p.y + qz*p.z;       // FROZEN arithmetic
            float d   = s1 - 2.0f*dot + p.w;
            if (__any_sync(0xffffffffu, d < best[KNN-1])) {
                if (d < best[KNN-1]) {
                    float cd = d; int ci = base + t;
#pragma unroll
                    for (int s = 0; s < KNN; s++) {
                        if (cd < best[s]) {
                            float td = best[s]; int ti = bid[s];
                            best[s] = cd; bid[s] = ci;
                            cd = td; ci = ti;
                        }
                    }
                }
            }
        }
    }

    __syncthreads();
    float* ld = (float*)sref;
    int*   li = (int*)(ld + 4096);
#pragma unroll
    for (int j = 0; j < KNN; j++) {
        int e = qslot*32 + half*16 + j;
        ld[e] = best[j]; li[e] = bid[j];
    }
    __syncthreads();
    if (half == 0) {
        const float* dA = ld + qslot*32;
        const float* dB = dA + 16;
        const int*   xA = li + qslot*32;
        const int*   xB = xA + 16;
        int ia = 0, ib = 0;
        int* op = out + ((size_t)b * Q + qi) * KNN;
#pragma unroll
        for (int r = 0; r < KNN; r++) {
            float da = dA[ia], db = dB[ib];
            bool tb = (db < da) || (db == da && xB[ib] < xA[ia]);
            op[r] = tb ? xB[ib] : xA[ia];
            if (tb) ib++; else ia++;
        }
    }
}

// ---------------- FPS: register data, ONE barrier/iter (double-buffered) ------
// Selection semantics identical: warp REDUX (max bits, min idx), then every
// warp redundantly reduces the 32 warp winners -> sel in registers everywhere.
// rv/ri double-buffered so the single barrier also fences the next iteration's
// winner writes.
__global__ void __launch_bounds__(1024) fps_kernel(const float* __restrict__ xyzp)
{
    extern __shared__ float sm[];
    float* sx = sm;
    float* sy = sm + NN;
    float* sz = sm + 2*NN;
    __shared__ float rv[2][32];
    __shared__ int   ri[2][32];

    int b = blockIdx.x, tid = threadIdx.x;
    int lane = tid & 31, wid = tid >> 5;
    const float* xb = xyzp + (size_t)b * NN * 4;

    float x0 = xb[0], y0 = xb[1], z0 = xb[2];
    float xr[8], yr[8], zr[8], dmin[8];
    float bv = -1.f; int bi = 0;
#pragma unroll
    for (int u = 0; u < 8; u++) {
        int i = tid + u*1024;
        float x = xb[i*4+0], y = xb[i*4+1], z = xb[i*4+2];
        sx[i] = x; sy[i] = y; sz[i] = z;
        xr[u] = x; yr[u] = y; zr[u] = z;
        float dx = x - x0, dy = y - y0, dz = z - z0;
        float d = dx*dx + dy*dy + dz*dz;
        dmin[u] = d;
        if (d > bv) { bv = d; bi = i; }
    }
    if (tid == 0) d_down_idx[b*NDWN] = 0;

    for (int s = 1; s < NDWN; s++) {
        int buf = s & 1;
        // level 1: warp (max value, min index)
        {
            unsigned key  = __float_as_uint(bv);                 // bv >= 0
            unsigned kmax = __reduce_max_sync(0xffffffffu, key);
            unsigned cidx = (key == kmax) ? (unsigned)bi : 0xffffffffu;
            unsigned imin = __reduce_min_sync(0xffffffffu, cidx);
            if (lane == 0) { rv[buf][wid] = __uint_as_float(kmax); ri[buf][wid] = (int)imin; }
        }
        __syncthreads();
        // level 2: every warp reduces the 32 warp winners redundantly
        int sel;
        {
            float v = rv[buf][lane]; int ii = ri[buf][lane];
            unsigned key  = __float_as_uint(v);
            unsigned kmax = __reduce_max_sync(0xffffffffu, key);
            unsigned cidx = (key == kmax) ? (unsigned)ii : 0xffffffffu;
            sel = (int)__reduce_min_sync(0xffffffffu, cidx);
        }
        if (tid == 0) d_down_idx[b*NDWN + s] = sel;
        float px = sx[sel], py = sy[sel], pz = sz[sel];
        bv = -1.f; bi = 0;
#pragma unroll
        for (int u = 0; u < 8; u++) {
            int i = tid + u*1024;
            float dx = xr[u]-px, dy = yr[u]-py, dz = zr[u]-pz;
            float d  = dx*dx + dy*dy + dz*dz;
            float v  = fminf(dmin[u], d);
            dmin[u]  = v;
            if (v > bv) { bv = v; bi = i; }
        }
        // no second barrier: next iteration writes rv[buf^1]; the barrier in
        // that iteration fences readers of this buffer two iterations out.
    }
}

__global__ void gather_down_kernel(const float* __restrict__ xyzp)
{
    int t = blockIdx.x * blockDim.x + threadIdx.x;
    if (t < BB*NDWN) {
        int b = t / NDWN;
        int id = d_down_idx[t];
        const float* src = xyzp + ((size_t)b * NN + id) * 4;
        float* dst = d_down_xyzp + (size_t)t * 4;
        dst[0]=src[0]; dst[1]=src[1]; dst[2]=src[2]; dst[3]=src[3];
    }
}

// ---------------- shared GEMM inner-compute (FROZEN) --------------------------
__device__ __forceinline__ void gemm_tile_compute(
    const float (*As)[132], const float (*Ws)[128],
    int tm, int tn, unsigned long long (&acc2)[8][4])
{
#pragma unroll
    for (int k = 0; k < 16; k++) {
        unsigned long long w2[4];
        float4 wv0 = *reinterpret_cast<const float4*>(&Ws[k][tn]);
        float4 wv1 = *reinterpret_cast<const float4*>(&Ws[k][tn+4]);
        w2[0] = pack2(wv0.x, wv0.y); w2[1] = pack2(wv0.z, wv0.w);
        w2[2] = pack2(wv1.x, wv1.y); w2[3] = pack2(wv1.z, wv1.w);
        float4 av0 = *reinterpret_cast<const float4*>(&As[k][tm]);
        float4 av1 = *reinterpret_cast<const float4*>(&As[k][tm+4]);
        unsigned long long a2[8];
        a2[0]=pack2(av0.x,av0.x); a2[1]=pack2(av0.y,av0.y);
        a2[2]=pack2(av0.z,av0.z); a2[3]=pack2(av0.w,av0.w);
        a2[4]=pack2(av1.x,av1.x); a2[5]=pack2(av1.y,av1.y);
        a2[6]=pack2(av1.z,av1.z); a2[7]=pack2(av1.w,av1.w);
#pragma unroll
        for (int i = 0; i < 8; i++)
#pragma unroll
            for (int jp = 0; jp < 4; jp++)
                ffma2(acc2[i][jp], a2[i], w2[jp]);
    }
}

// ---------------- generic fp32 tiled GEMM (FROZEN from R13) -------------------
template<bool RELU>
__global__ void __launch_bounds__(256) gemm_kernel(
    const float* __restrict__ A, const float* __restrict__ W,
    const float* __restrict__ bias, float* __restrict__ C,
    int M, int K, int Nc)
{
    __shared__ float As[2][16][132];
    __shared__ float Ws[2][16][128];
    int bm = blockIdx.y * 128, bn = blockIdx.x * 128;
    int tid = threadIdx.x;
    int tm = (tid / 16) * 8, tn = (tid % 16) * 8;
    int m0 = tid >> 2, k4 = tid & 3;
    int wk = tid >> 5, wn = tid & 31;

    unsigned long long acc2[8][4];
#pragma unroll
    for (int i = 0; i < 8; i++)
#pragma unroll
        for (int jp = 0; jp < 4; jp++) acc2[i][jp] = 0ull;

    {
        float4 v0 = *reinterpret_cast<const float4*>(A + (size_t)(bm+m0)*K + k4*4);
        float4 v1 = *reinterpret_cast<const float4*>(A + (size_t)(bm+m0+64)*K + k4*4);
        As[0][k4*4+0][m0] = v0.x; As[0][k4*4+1][m0] = v0.y;
        As[0][k4*4+2][m0] = v0.z; As[0][k4*4+3][m0] = v0.w;
        As[0][k4*4+0][m0+64] = v1.x; As[0][k4*4+1][m0+64] = v1.y;
        As[0][k4*4+2][m0+64] = v1.z; As[0][k4*4+3][m0+64] = v1.w;
        cp_async16(&Ws[0][wk][wn*4],   W + (size_t)wk*Nc + bn + wn*4);
        cp_async16(&Ws[0][wk+8][wn*4], W + (size_t)(wk+8)*Nc + bn + wn*4);
        CP_ASYNC_COMMIT(); CP_ASYNC_WAIT_ALL();
    }
    __syncthreads();

    int nsteps = K >> 4;
    for (int s = 0; s < nsteps; s++) {
        int cur = s & 1, nxt = cur ^ 1;
        bool pre = (s + 1 < nsteps);
        float4 p0, p1;
        if (pre) {
            int k0n = (s + 1) << 4;
            p0 = *reinterpret_cast<const float4*>(A + (size_t)(bm+m0)*K + k0n + k4*4);
            p1 = *reinterpret_cast<const float4*>(A + (size_t)(bm+m0+64)*K + k0n + k4*4);
            cp_async16(&Ws[nxt][wk][wn*4],   W + (size_t)(k0n+wk)*Nc + bn + wn*4);
            cp_async16(&Ws[nxt][wk+8][wn*4], W + (size_t)(k0n+wk+8)*Nc + bn + wn*4);
            CP_ASYNC_COMMIT();
        }
        gemm_tile_compute(As[cur], Ws[cur], tm, tn, acc2);
        if (pre) {
            As[nxt][k4*4+0][m0] = p0.x; As[nxt][k4*4+1][m0] = p0.y;
            As[nxt][k4*4+2][m0] = p0.z; As[nxt][k4*4+3][m0] = p0.w;
            As[nxt][k4*4+0][m0+64] = p1.x; As[nxt][k4*4+1][m0+64] = p1.y;
            As[nxt][k4*4+2][m0+64] = p1.z; As[nxt][k4*4+3][m0+64] = p1.w;
            CP_ASYNC_WAIT_ALL();
        }
        __syncthreads();
    }
#pragma unroll
    for (int i = 0; i < 8; i++)
#pragma unroll
        for (int jp = 0; jp < 4; jp++) {
            float lo, hi;
            unpack2(acc2[i][jp], lo, hi);
            float v0 = lo + bias[bn+tn+2*jp];
            float v1 = hi + bias[bn+tn+2*jp+1];
            if (RELU) { v0 = fmaxf(v0, 0.f); v1 = fmaxf(v1, 0.f); }
            float2 st; st.x = v0; st.y = v1;
            *reinterpret_cast<float2*>(&C[(size_t)(bm+tm+i)*Nc + bn+tn+2*jp]) = st;
        }
}

// ---------------- fused dual-QKV GEMM (FROZEN from R13) -----------------------
__global__ void __launch_bounds__(256) gemm_qkv2_kernel(
    const float* __restrict__ A,
    const float* __restrict__ Wl, const float* __restrict__ bl,
    const float* __restrict__ Wg, const float* __restrict__ bg,
    float* __restrict__ Cl, float* __restrict__ Cg,
    int M, int K)
{
    __shared__ float As[2][16][132];
    __shared__ float Ws[2][16][128];
    int bm = blockIdx.y * 128;
    int bnRaw = blockIdx.x * 128;
    bool isL = bnRaw < QKVD;
    const float* W    = isL ? Wl : Wg;
    const float* bias = isL ? bl : bg;
    float*       C    = isL ? Cl : Cg;
    int bn = isL ? bnRaw : bnRaw - QKVD;
    const int Nc = QKVD;
    int tid = threadIdx.x;
    int tm = (tid / 16) * 8, tn = (tid % 16) * 8;
    int m0 = tid >> 2, k4 = tid & 3;
    int wk = tid >> 5, wn = tid & 31;

    unsigned long long acc2[8][4];
#pragma unroll
    for (int i = 0; i < 8; i++)
#pragma unroll
        for (int jp = 0; jp < 4; jp++) acc2[i][jp] = 0ull;

    {
        float4 v0 = *reinterpret_cast<const float4*>(A + (size_t)(bm+m0)*K + k4*4);
        float4 v1 = *reinterpret_cast<const float4*>(A + (size_t)(bm+m0+64)*K + k4*4);
        As[0][k4*4+0][m0] = v0.x; As[0][k4*4+1][m0] = v0.y;
        As[0][k4*4+2][m0] = v0.z; As[0][k4*4+3][m0] = v0.w;
        As[0][k4*4+0][m0+64] = v1.x; As[0][k4*4+1][m0+64] = v1.y;
        As[0][k4*4+2][m0+64] = v1.z; As[0][k4*4+3][m0+64] = v1.w;
        cp_async16(&Ws[0][wk][wn*4],   W + (size_t)wk*Nc + bn + wn*4);
        cp_async16(&Ws[0][wk+8][wn*4], W + (size_t)(wk+8)*Nc + bn + wn*4);
        CP_ASYNC_COMMIT(); CP_ASYNC_WAIT_ALL();
    }
    __syncthreads();

    int nsteps = K >> 4;
    for (int s = 0; s < nsteps; s++) {
        int cur = s & 1, nxt = cur ^ 1;
        bool pre = (s + 1 < nsteps);
        float4 p0, p1;
        if (pre) {
            int k0n = (s + 1) << 4;
            p0 = *reinterpret_cast<const float4*>(A + (size_t)(bm+m0)*K + k0n + k4*4);
            p1 = *reinterpret_cast<const float4*>(A + (size_t)(bm+m0+64)*K + k0n + k4*4);
            cp_async16(&Ws[nxt][wk][wn*4],   W + (size_t)(k0n+wk)*Nc + bn + wn*4);
            cp_async16(&Ws[nxt][wk+8][wn*4], W + (size_t)(k0n+wk+8)*Nc + bn + wn*4);
            CP_ASYNC_COMMIT();
        }
        gemm_tile_compute(As[cur], Ws[cur], tm, tn, acc2);
        if (pre) {
            As[nxt][k4*4+0][m0] = p0.x; As[nxt][k4*4+1][m0] = p0.y;
            As[nxt][k4*4+2][m0] = p0.z; As[nxt][k4*4+3][m0] = p0.w;
            As[nxt][k4*4+0][m0+64] = p1.x; As[nxt][k4*4+1][m0+64] = p1.y;
            As[nxt][k4*4+2][m0+64] = p1.z; As[nxt][k4*4+3][m0+64] = p1.w;
            CP_ASYNC_WAIT_ALL();
        }
        __syncthreads();
    }
#pragma unroll
    for (int i = 0; i < 8; i++)
#pragma unroll
        for (int jp = 0; jp < 4; jp++) {
            float lo, hi;
            unpack2(acc2[i][jp], lo, hi);
            float2 st;
            st.x = lo + bias[bn+tn+2*jp];
            st.y = hi + bias[bn+tn+2*jp+1];
            *reinterpret_cast<float2*>(&C[(size_t)(bm+tm+i)*Nc + bn+tn+2*jp]) = st;
        }
}

// ---------------- split projection-1 GEMM (FROZEN from R13) -------------------
template<int PHASE>
__global__ void __launch_bounds__(256) gemm_proj1_kernel(
    const float* __restrict__ A, int lda,
    const float* __restrict__ W,
    const float* __restrict__ bias,
    float* __restrict__ C,
    int M, int K, int Nc)
{
    __shared__ float As[2][16][132];
    __shared__ float Ws[2][16][128];
    int bm = blockIdx.y * 128, bn = blockIdx.x * 128;
    int tid = threadIdx.x;
    int tm = (tid / 16) * 8, tn = (tid % 16) * 8;
    int m0 = tid >> 2, k4 = tid & 3;
    int wk = tid >> 5, wn = tid & 31;

    unsigned long long acc2[8][4];
#pragma unroll
    for (int i = 0; i < 8; i++)
#pragma unroll
        for (int jp = 0; jp < 4; jp++) acc2[i][jp] = 0ull;

    {
        float4 v0 = *reinterpret_cast<const float4*>(A + (size_t)(bm+m0)*lda + k4*4);
        float4 v1 = *reinterpret_cast<const float4*>(A + (size_t)(bm+m0+64)*lda + k4*4);
        As[0][k4*4+0][m0] = v0.x; As[0][k4*4+1][m0] = v0.y;
        As[0][k4*4+2][m0] = v0.z; As[0][k4*4+3][m0] = v0.w;
        As[0][k4*4+0][m0+64] = v1.x; As[0][k4*4+1][m0+64] = v1.y;
        As[0][k4*4+2][m0+64] = v1.z; As[0][k4*4+3][m0+64] = v1.w;
        cp_async16(&Ws[0][wk][wn*4],   W + (size_t)wk*Nc + bn + wn*4);
        cp_async16(&Ws[0][wk+8][wn*4], W + (size_t)(wk+8)*Nc + bn + wn*4);
        CP_ASYNC_COMMIT(); CP_ASYNC_WAIT_ALL();
    }
    __syncthreads();

    int nsteps = K >> 4;
    for (int s = 0; s < nsteps; s++) {
        int cur = s & 1, nxt = cur ^ 1;
        bool pre = (s + 1 < nsteps);
        float4 p0, p1;
        if (pre) {
            int k0n = (s + 1) << 4;
            p0 = *reinterpret_cast<const float4*>(A + (size_t)(bm+m0)*lda + k0n + k4*4);
            p1 = *reinterpret_cast<const float4*>(A + (size_t)(bm+m0+64)*lda + k0n + k4*4);
            cp_async16(&Ws[nxt][wk][wn*4],   W + (size_t)(k0n+wk)*Nc + bn + wn*4);
            cp_async16(&Ws[nxt][wk+8][wn*4], W + (size_t)(k0n+wk+8)*Nc + bn + wn*4);
            CP_ASYNC_COMMIT();
        }
        gemm_tile_compute(As[cur], Ws[cur], tm, tn, acc2);
        if (pre) {
            As[nxt][k4*4+0][m0] = p0.x; As[nxt][k4*4+1][m0] = p0.y;
            As[nxt][k4*4+2][m0] = p0.z; As[nxt][k4*4+3][m0] = p0.w;
            As[nxt][k4*4+0][m0+64] = p1.x; As[nxt][k4*4+1][m0+64] = p1.y;
            As[nxt][k4*4+2][m0+64] = p1.z; As[nxt][k4*4+3][m0+64] = p1.w;
            CP_ASYNC_WAIT_ALL();
        }
        __syncthreads();
    }
#pragma unroll
    for (int i = 0; i < 8; i++)
#pragma unroll
        for (int jp = 0; jp < 4; jp++) {
            float lo, hi;
            unpack2(acc2[i][jp], lo, hi);
            float* cp = &C[(size_t)(bm+tm+i)*Nc + bn+tn+2*jp];
            if (PHASE == 0) {
                float2 st;
                st.x = lo + bias[bn+tn+2*jp];
                st.y = hi + bias[bn+tn+2*jp+1];
                *reinterpret_cast<float2*>(cp) = st;
            } else {
                float2 prev = *reinterpret_cast<const float2*>(cp);
                float2 st;
                st.x = fmaxf(prev.x + lo, 0.f);
                st.y = fmaxf(prev.y + hi, 0.f);
                *reinterpret_cast<float2*>(cp) = st;
            }
        }
}

// ---------------- PE GEMM (FROZEN from R13) -----------------------------------
__global__ void __launch_bounds__(256) gemm_pe_kernel(
    const float* __restrict__ xyzp,
    const float* __restrict__ nbr, int nbr_rows,
    const int* __restrict__ nidx,
    const float* __restrict__ w1, const float* __restrict__ b1,
    const float* __restrict__ w2, const float* __restrict__ b2,
    float* __restrict__ pos)
{
    __shared__ float As[2][16][132];
    __shared__ float Ws[2][16][128];
    __shared__ float xd[128][5];
    __shared__ float w1s[4][128];
    __shared__ float b1s[128];

    int bm = blockIdx.x * 128;
    int tid = threadIdx.x;
    int wk = tid >> 5, wn = tid & 31;

    for (int t = tid; t < 512; t += 256) w1s[t >> 7][t & 127] = w1[t];
    if (tid < 128) b1s[tid] = b1[tid];
    if (tid < 128) {
        int r  = bm + tid;
        int pi = r >> 4;
        int j  = r & 15;
        int b  = pi / NN;
        int id = nidx[(size_t)pi*KNN + j];
        const float* qp = xyzp + (size_t)pi * 4;
        const float* np = nbr + ((size_t)b * nbr_rows + id) * 4;
        xd[tid][0] = qp[0]-np[0]; xd[tid][1] = qp[1]-np[1];
        xd[tid][2] = qp[2]-np[2]; xd[tid][3] = qp[3]-np[3];
    }
    __syncthreads();

    int tm = (tid / 16) * 8, tn = (tid % 16) * 8;
    unsigned long long acc2[8][4];
#pragma unroll
    for (int i = 0; i < 8; i++)
#pragma unroll
        for (int jp = 0; jp < 4; jp++) acc2[i][jp] = 0ull;

#pragma unroll
    for (int t = tid; t < 2048; t += 256) {
        int m = t & 127, k = t >> 7;
        int kk = k;
        float hv = b1s[kk] + xd[m][0]*w1s[0][kk] + xd[m][1]*w1s[1][kk]
                           + xd[m][2]*w1s[2][kk] + xd[m][3]*w1s[3][kk];
        As[0][k][m] = fmaxf(hv, 0.f);
    }
    cp_async16(&Ws[0][wk][wn*4],   w2 + (size_t)wk*128 + wn*4);
    cp_async16(&Ws[0][wk+8][wn*4], w2 + (size_t)(wk+8)*128 + wn*4);
    CP_ASYNC_COMMIT(); CP_ASYNC_WAIT_ALL();
    __syncthreads();

    for (int s = 0; s < 8; s++) {
        int cur = s & 1, nxt = cur ^ 1;
        bool pre = (s + 1 < 8);
        if (pre) {
            int k0n = (s + 1) << 4;
            cp_async16(&Ws[nxt][wk][wn*4],   w2 + (size_t)(k0n+wk)*128 + wn*4);
            cp_async16(&Ws[nxt][wk+8][wn*4], w2 + (size_t)(k0n+wk+8)*128 + wn*4);
            CP_ASYNC_COMMIT();
#pragma unroll
            for (int t = tid; t < 2048; t += 256) {
                int m = t & 127, k = t >> 7;
                int kk = k0n + k;
                float hv = b1s[kk] + xd[m][0]*w1s[0][kk] + xd[m][1]*w1s[1][kk]
                                   + xd[m][2]*w1s[2][kk] + xd[m][3]*w1s[3][kk];
                As[nxt][k][m] = fmaxf(hv, 0.f);
            }
        }
        gemm_tile_compute(As[cur], Ws[cur], tm, tn, acc2);
        if (pre) CP_ASYNC_WAIT_ALL();
        __syncthreads();
    }
#pragma unroll
    for (int i = 0; i < 8; i++)
#pragma unroll
        for (int jp = 0; jp < 4; jp++) {
            float lo, hi;
            unpack2(acc2[i][jp], lo, hi);
            float2 st;
            st.x = lo + b2[tn+2*jp];
            st.y = hi + b2[tn+2*jp+1];
            *reinterpret_cast<float2*>(&pos[(size_t)(bm+tm+i)*128 + tn+2*jp]) = st;
        }
}

// ---------------- kvmax (FROZEN) ----------------------------------------------
__global__ void __launch_bounds__(128) kvmax_kernel()
{
    int b = blockIdx.y, r = blockIdx.x, c = threadIdx.x;
    int src = d_down_idx[b*NDWN + r];
    const int* pidx = d_idx_l + ((size_t)b*NN + src)*KNN;
    float km = -3.4e38f, vm = -3.4e38f;
#pragma unroll
    for (int j = 0; j < KNN; j++) {
        int id = pidx[j];
        const float* row = d_qkv_g + ((size_t)b*NN + id)*QKVD;
        km = fmaxf(km, row[AD   + c]);
        vm = fmaxf(vm, row[2*AD + c]);
    }
    d_kmax[((size_t)b*NDWN + r)*AD + c] = km;
    d_vmax[((size_t)b*NDWN + r)*AD + c] = vm;
}

// ---------------- attention (FROZEN block version from R12/R13) ---------------
__global__ void __launch_bounds__(128) attn_kernel(
    const int*  __restrict__ nidx,
    const float* __restrict__ qsrc,  int qstride,
    const float* __restrict__ kbase, const float* __restrict__ vbase,
    int kv_stride, int kv_rows,
    const float* __restrict__ pos,
    const float* __restrict__ fg,  const float* __restrict__ fb,
    float* __restrict__ out, int out_coloff)
{
    __shared__ float ts[KNN*128];
    __shared__ int   sidx[KNN];
    __shared__ float m_s[KNN], i_s[KNN];

    int b = blockIdx.y;
    int c = threadIdx.x;
    int lane = c & 31, warp = c >> 5;
    float gr = fg[c], br = fb[c];
    const float inv_scale = 0.08838834764831845f;

    for (int pp = 0; pp < PPB; pp++) {
        int i = blockIdx.x * PPB + pp;
        size_t bi = (size_t)b * NN + i;

        if (c < KNN) sidx[c] = nidx[bi*KNN + c];
        __syncthreads();

        float qv = qsrc[bi*qstride + c];
        const float* prow = pos + bi * (KNN*128) + c;
        float tr[KNN], vp[KNN];
#pragma unroll
        for (int j = 0; j < KNN; j++) {
            size_t kr = ((size_t)b*kv_rows + sidx[j]) * kv_stride;
            float pv = prow[j*128];
            tr[j] = qv - kbase[kr + c] + pv;
            vp[j] = vbase[kr + c] + pv;
            ts[j*128 + c] = tr[j];
        }
        __syncthreads();

#pragma unroll
        for (int jj = 0; jj < 4; jj++) {
            int j = warp*4 + jj;
            float v0 = ts[j*128+lane],    v1 = ts[j*128+lane+32];
            float v2 = ts[j*128+lane+64], v3 = ts[j*128+lane+96];
            float s  = v0+v1+v2+v3;
            float ss = v0*v0+v1*v1+v2*v2+v3*v3;
#pragma unroll
            for (int off = 16; off; off >>= 1) {
                s  += __shfl_xor_sync(0xffffffffu, s,  off);
                ss += __shfl_xor_sync(0xffffffffu, ss, off);
            }
            if (lane == 0) {
                float m   = s * (1.f/128.f);
                float var = ss * (1.f/128.f) - m*m;
                if (var < 0.f) var = 0.f;
                m_s[j] = m;
                i_s[j] = 1.f / sqrtf(var + 1e-5f);
            }
        }
        __syncthreads();

        float a[KNN], mx = -3.4e38f;
#pragma unroll
        for (int j = 0; j < KNN; j++) {
            a[j] = ((tr[j] - m_s[j]) * i_s[j] * gr + br) * inv_scale;
            mx = fmaxf(mx, a[j]);
        }
        float se = 0.f, ov = 0.f;
#pragma unroll
        for (int j = 0; j < KNN; j++) {
            float e = expf(a[j] - mx);
            se += e;
            ov += e * vp[j];
        }
        out[bi*(2*AD) + out_coloff + c] = ov / se;
        __syncthreads();
    }
}

// ---------------- launcher ----------------------------------------------------
extern "C" void kernel_launch(void* const* d_in, const int* in_sizes, int n_in,
                              void* d_out, int out_size)
{
    const float* xyzp     = (const float*)d_in[0];
    const float* features = (const float*)d_in[1];
    const float* l_qkv_w  = (const float*)d_in[2];
    const float* l_qkv_b  = (const float*)d_in[3];
    const float* l_pe_w1  = (const float*)d_in[4];
    const float* l_pe_b1  = (const float*)d_in[5];
    const float* l_pe_w2  = (const float*)d_in[6];
    const float* l_pe_b2  = (const float*)d_in[7];
    const float* l_fc_g   = (const float*)d_in[8];
    const float* l_fc_b   = (const float*)d_in[9];
    const float* g_qkv_w  = (const float*)d_in[10];
    const float* g_qkv_b  = (const float*)d_in[11];
    const float* g_pe_w1  = (const float*)d_in[12];
    const float* g_pe_b1  = (const float*)d_in[13];
    const float* g_pe_w2  = (const float*)d_in[14];
    const float* g_pe_b2  = (const float*)d_in[15];
    const float* g_fc_g   = (const float*)d_in[16];
    const float* g_fc_b   = (const float*)d_in[17];
    const float* proj_w1  = (const float*)d_in[18];
    const float* proj_b1  = (const float*)d_in[19];
    const float* proj_w2  = (const float*)d_in[20];
    const float* proj_b2  = (const float*)d_in[21];
    float* out = (float*)d_out;

    float *qkv_l, *qkv_g, *cat_p, *hid_p, *kmax_p, *vmax_p, *dxyzp_p, *posl_p, *posg_p;
    int *idx_l, *idx_inv;
    cudaGetSymbolAddress((void**)&qkv_l,   d_qkv_l);
    cudaGetSymbolAddress((void**)&qkv_g,   d_qkv_g);
    cudaGetSymbolAddress((void**)&cat_p,   d_cat);
    cudaGetSymbolAddress((void**)&hid_p,   d_hid);
    cudaGetSymbolAddress((void**)&kmax_p,  d_kmax);
    cudaGetSymbolAddress((void**)&vmax_p,  d_vmax);
    cudaGetSymbolAddress((void**)&dxyzp_p, d_down_xyzp);
    cudaGetSymbolAddress((void**)&posl_p,  d_pos_l);
    cudaGetSymbolAddress((void**)&posg_p,  d_pos_g);
    cudaGetSymbolAddress((void**)&idx_l,   d_idx_l);
    cudaGetSymbolAddress((void**)&idx_inv, d_idx_inv);

    const int FPS_SMEM = 3 * NN * (int)sizeof(float);   // xyz only; dmin in regs
    cudaFuncSetAttribute(fps_kernel, cudaFuncAttributeMaxDynamicSharedMemorySize, FPS_SMEM);

    static cudaStream_t sA = 0, sB = 0, sC = 0;
    static cudaEvent_t evRoot, evDown, evKNN, evQKV, evPl, evB, evC;
    static bool inited = false;
    if (!inited) {
        int leastP = 0, greatestP = 0;
        cudaDeviceGetStreamPriorityRange(&leastP, &greatestP);
        cudaStreamCreateWithPriority(&sA, cudaStreamNonBlocking, leastP);
        cudaStreamCreateWithPriority(&sB, cudaStreamNonBlocking, greatestP);
        cudaStreamCreateWithPriority(&sC, cudaStreamNonBlocking, greatestP);
        cudaEventCreateWithFlags(&evRoot, cudaEventDisableTiming);
        cudaEventCreateWithFlags(&evDown, cudaEventDisableTiming);
        cudaEventCreateWithFlags(&evKNN,  cudaEventDisableTiming);
        cudaEventCreateWithFlags(&evQKV,  cudaEventDisableTiming);
        cudaEventCreateWithFlags(&evPl,   cudaEventDisableTiming);
        cudaEventCreateWithFlags(&evB,    cudaEventDisableTiming);
        cudaEventCreateWithFlags(&evC,    cudaEventDisableTiming);
        inited = true;
    }

    const int M = BB * NN;
    const int PE_BLOCKS = (BB*NN*KNN) / 128;   // 2048

    cudaEventRecord(evRoot, 0);
    cudaStreamWaitEvent(sA, evRoot, 0);
    cudaStreamWaitEvent(sB, evRoot, 0);

    // sA: self-KNN (split) -> PE-local
    knn_kernel<<<dim3(NN/128, BB), 256, 0, sA>>>(xyzp, NN, xyzp, NN, idx_l);
    cudaEventRecord(evKNN, sA);
    gemm_pe_kernel<<<PE_BLOCKS, 256, 0, sA>>>(xyzp, xyzp, NN, idx_l,
                                              l_pe_w1, l_pe_b1, l_pe_w2, l_pe_b2, posl_p);

    // sB: FPS -> gather (fork sC after down points ready)
    fps_kernel<<<BB, 1024, FPS_SMEM, sB>>>(xyzp);
    gather_down_kernel<<<(BB*NDWN + 255)/256, 256, 0, sB>>>(xyzp);
    cudaEventRecord(evDown, sB);
    cudaStreamWaitEvent(sC, evDown, 0);

    // sC: inv-KNN (split) -> PE-global
    knn_kernel<<<dim3(NN/128, BB), 256, 0, sC>>>(xyzp, NN, dxyzp_p, NDWN, idx_inv);
    gemm_pe_kernel<<<PE_BLOCKS, 256, 0, sC>>>(xyzp, dxyzp_p, NDWN, idx_inv,
                                              g_pe_w1, g_pe_b1, g_pe_w2, g_pe_b2, posg_p);

    // default: fused dual-QKV GEMM
    gemm_qkv2_kernel<<<dim3(2*QKVD/128, M/128), 256>>>(features,
                                                       l_qkv_w, l_qkv_b,
                                                       g_qkv_w, g_qkv_b,
                                                       qkv_l, qkv_g, M, DIMF);
    cudaEventRecord(evQKV, 0);

    // sA: local attention, then proj1 local half
    cudaStreamWaitEvent(sA, evQKV, 0);
    attn_kernel<<<dim3(NN/PPB, BB), 128, 0, sA>>>(idx_l, qkv_l, QKVD,
                                                  qkv_l + AD, qkv_l + 2*AD, QKVD, NN,
                                                  posl_p, l_fc_g, l_fc_b, cat_p, 0);
    gemm_proj1_kernel<0><<<dim3(DIMF/128, M/128), 256, 0, sA>>>(
        cat_p, 2*AD, proj_w1, proj_b1, hid_p, M, AD, DIMF);
    cudaEventRecord(evPl, sA);

    // sB: kvmax
    cudaStreamWaitEvent(sB, evKNN, 0);
    cudaStreamWaitEvent(sB, evQKV, 0);
    kvmax_kernel<<<dim3(NDWN, BB), 128, 0, sB>>>();
    cudaEventRecord(evB, sB);

    // sC: global attention
    cudaStreamWaitEvent(sC, evB, 0);
    attn_kernel<<<dim3(NN/PPB, BB), 128, 0, sC>>>(idx_inv, qkv_g, QKVD,
                                                  kmax_p, vmax_p, AD, NDWN,
                                                  posg_p, g_fc_g, g_fc_b, cat_p, AD);
    cudaEventRecord(evC, sC);

    // default: join, proj1 global-half accumulate+relu, then proj2
    cudaStreamWaitEvent(0, evPl, 0);
    cudaStreamWaitEvent(0, evC, 0);
    gemm_proj1_kernel<1><<<dim3(DIMF/128, M/128), 256>>>(
        cat_p + AD, 2*AD, proj_w1 + (size_t)AD*DIMF, proj_b1, hid_p, M, AD, DIMF);
    gemm_kernel<false><<<dim3(DIMF/128, M/128), 256>>>(hid_p, proj_w2, proj_b2, out, M, DIMF, DIMF);

    (void)in_sizes; (void)n_in; (void)out_size;
}

// round 16
// speedup vs baseline: 1.1111x; 1.0504x over previous
#include <cuda_runtime.h>
#include <math.h>

#define BB    2
#define NN    8192
#define NDWN  1024
#define KNN   16
#define AD    128
#define QKVD  384
#define DIMF  256
#define PPB   8

// ---------------- packed fp32 helpers (Blackwell FFMA2) -----------------------
__device__ __forceinline__ void ffma2(unsigned long long &acc,
                                      unsigned long long a,
                                      unsigned long long w) {
    asm("fma.rn.f32x2 %0, %1, %2, %3;" : "=l"(acc) : "l"(a), "l"(w), "l"(acc));
}
__device__ __forceinline__ unsigned long long pack2(float lo, float hi) {
    unsigned long long r;
    asm("mov.b64 %0, {%1, %2};" : "=l"(r) : "f"(lo), "f"(hi));
    return r;
}
__device__ __forceinline__ void unpack2(unsigned long long v, float &lo, float &hi) {
    asm("mov.b64 {%0, %1}, %2;" : "=f"(lo), "=f"(hi) : "l"(v));
}

// ---------------- cp.async helpers --------------------------------------------
__device__ __forceinline__ void cp_async16(void* smem, const void* gmem) {
    unsigned s = (unsigned)__cvta_generic_to_shared(smem);
    asm volatile("cp.async.ca.shared.global [%0], [%1], 16;\n" :: "r"(s), "l"(gmem));
}
#define CP_ASYNC_COMMIT()   asm volatile("cp.async.commit_group;\n" ::: "memory")
#define CP_ASYNC_WAIT_ALL() asm volatile("cp.async.wait_group 0;\n" ::: "memory")

// ---------------- device scratch ---------------------------------------------
__device__ float d_qkv_l[BB*NN*QKVD];
__device__ float d_qkv_g[BB*NN*QKVD];
__device__ float d_cat  [BB*NN*2*AD];
__device__ float d_hid  [BB*NN*DIMF];
__device__ float d_kmax [BB*NDWN*AD];
__device__ float d_vmax [BB*NDWN*AD];
__device__ float d_down_xyzp[BB*NDWN*4];
__device__ float d_pos_l[(size_t)BB*NN*KNN*AD];
__device__ float d_pos_g[(size_t)BB*NN*KNN*AD];
__device__ int   d_idx_l  [BB*NN*KNN];
__device__ int   d_idx_inv[BB*NN*KNN];
__device__ int   d_down_idx[BB*NDWN];

// ---------------- KNN: FROZEN byte-for-byte from R11 --------------------------
__global__ void __launch_bounds__(256) knn_kernel(
    const float* __restrict__ qpts, int Q,
    const float* __restrict__ rpts, int R,
    int* __restrict__ out)
{
    __shared__ float4 sref[2048];           // two half-tiles of 1024 (32 KB)
    int b = blockIdx.y;
    const float* qb = qpts + (size_t)b * Q * 4;
    const float* rb = rpts + (size_t)b * R * 4;
    int qslot = threadIdx.x & 127;
    int half  = threadIdx.x >> 7;
    int qi = blockIdx.x * 128 + qslot;
    int Rh = R >> 1;

    float qx = qb[qi*4+0], qy = qb[qi*4+1], qz = qb[qi*4+2];
    float s1 = qx*qx + qy*qy + qz*qz;

    float best[KNN];
    int   bid [KNN];
#pragma unroll
    for (int t = 0; t < KNN; t++) { best[t] = 3.4e38f; bid[t] = 0; }

    for (int off = 0; off < Rh; off += 1024) {
        int cnt = min(1024, Rh - off);
        __syncthreads();
        for (int t = threadIdx.x; t < 2048; t += 256) {
            int local = t & 1023;
            int th    = t >> 10;
            if (local < cnt) {
                float4 p = *reinterpret_cast<const float4*>(rb + (size_t)(th*Rh + off + local) * 4);
                p.w = p.x*p.x + p.y*p.y + p.z*p.z;
                sref[t] = p;
            }
        }
        __syncthreads();
        const float4* sp = sref + (half << 10);
        int base = half*Rh + off;
#pragma unroll 8
        for (int t = 0; t < cnt; t++) {
            float4 p = sp[t];
            float dot = qx*p.x + qy*p.y + qz*p.z;       // FROZEN arithmetic
            float d   = s1 - 2.0f*dot + p.w;
            if (__any_sync(0xffffffffu, d < best[KNN-1])) {
                if (d < best[KNN-1]) {
                    float cd = d; int ci = base + t;
#pragma unroll
                    for (int s = 0; s < KNN; s++) {
                        if (cd < best[s]) {
                            float td = best[s]; int ti = bid[s];
                            best[s] = cd; bid[s] = ci;
                            cd = td; ci = ti;
                        }
                    }
                }
            }
        }
    }

    __syncthreads();
    float* ld = (float*)sref;
    int*   li = (int*)(ld + 4096);
#pragma unroll
    for (int j = 0; j < KNN; j++) {
        int e = qslot*32 + half*16 + j;
        ld[e] = best[j]; li[e] = bid[j];
    }
    __syncthreads();
    if (half == 0) {
        const float* dA = ld + qslot*32;
        const float* dB = dA + 16;
        const int*   xA = li + qslot*32;
        const int*   xB = xA + 16;
        int ia = 0, ib = 0;
        int* op = out + ((size_t)b * Q + qi) * KNN;
#pragma unroll
        for (int r = 0; r < KNN; r++) {
            float da = dA[ia], db = dB[ib];
            bool tb = (db < da) || (db == da && xB[ib] < xA[ia]);
            op[r] = tb ? xB[ib] : xA[ia];
            if (tb) ib++; else ia++;
        }
    }
}

// ---------------- FPS: FROZEN from R15 ----------------------------------------
__global__ void __launch_bounds__(1024) fps_kernel(const float* __restrict__ xyzp)
{
    extern __shared__ float sm[];
    float* sx = sm;
    float* sy = sm + NN;
    float* sz = sm + 2*NN;
    __shared__ float rv[2][32];
    __shared__ int   ri[2][32];

    int b = blockIdx.x, tid = threadIdx.x;
    int lane = tid & 31, wid = tid >> 5;
    const float* xb = xyzp + (size_t)b * NN * 4;

    float x0 = xb[0], y0 = xb[1], z0 = xb[2];
    float xr[8], yr[8], zr[8], dmin[8];
    float bv = -1.f; int bi = 0;
#pragma unroll
    for (int u = 0; u < 8; u++) {
        int i = tid + u*1024;
        float x = xb[i*4+0], y = xb[i*4+1], z = xb[i*4+2];
        sx[i] = x; sy[i] = y; sz[i] = z;
        xr[u] = x; yr[u] = y; zr[u] = z;
        float dx = x - x0, dy = y - y0, dz = z - z0;
        float d = dx*dx + dy*dy + dz*dz;
        dmin[u] = d;
        if (d > bv) { bv = d; bi = i; }
    }
    if (tid == 0) d_down_idx[b*NDWN] = 0;

    for (int s = 1; s < NDWN; s++) {
        int buf = s & 1;
        {
            unsigned key  = __float_as_uint(bv);
            unsigned kmax = __reduce_max_sync(0xffffffffu, key);
            unsigned cidx = (key == kmax) ? (unsigned)bi : 0xffffffffu;
            unsigned imin = __reduce_min_sync(0xffffffffu, cidx);
            if (lane == 0) { rv[buf][wid] = __uint_as_float(kmax); ri[buf][wid] = (int)imin; }
        }
        __syncthreads();
        int sel;
        {
            float v = rv[buf][lane]; int ii = ri[buf][lane];
            unsigned key  = __float_as_uint(v);
            unsigned kmax = __reduce_max_sync(0xffffffffu, key);
            unsigned cidx = (key == kmax) ? (unsigned)ii : 0xffffffffu;
            sel = (int)__reduce_min_sync(0xffffffffu, cidx);
        }
        if (tid == 0) d_down_idx[b*NDWN + s] = sel;
        float px = sx[sel], py = sy[sel], pz = sz[sel];
        bv = -1.f; bi = 0;
#pragma unroll
        for (int u = 0; u < 8; u++) {
            int i = tid + u*1024;
            float dx = xr[u]-px, dy = yr[u]-py, dz = zr[u]-pz;
            float d  = dx*dx + dy*dy + dz*dz;
            float v  = fminf(dmin[u], d);
            dmin[u]  = v;
            if (v > bv) { bv = v; bi = i; }
        }
    }
}

__global__ void gather_down_kernel(const float* __restrict__ xyzp)
{
    int t = blockIdx.x * blockDim.x + threadIdx.x;
    if (t < BB*NDWN) {
        int b = t / NDWN;
        int id = d_down_idx[t];
        const float* src = xyzp + ((size_t)b * NN + id) * 4;
        float* dst = d_down_xyzp + (size_t)t * 4;
        dst[0]=src[0]; dst[1]=src[1]; dst[2]=src[2]; dst[3]=src[3];
    }
}

// ---------------- shared GEMM inner-compute (FROZEN) --------------------------
__device__ __forceinline__ void gemm_tile_compute(
    const float (*As)[132], const float (*Ws)[128],
    int tm, int tn, unsigned long long (&acc2)[8][4])
{
#pragma unroll
    for (int k = 0; k < 16; k++) {
        unsigned long long w2[4];
        float4 wv0 = *reinterpret_cast<const float4*>(&Ws[k][tn]);
        float4 wv1 = *reinterpret_cast<const float4*>(&Ws[k][tn+4]);
        w2[0] = pack2(wv0.x, wv0.y); w2[1] = pack2(wv0.z, wv0.w);
        w2[2] = pack2(wv1.x, wv1.y); w2[3] = pack2(wv1.z, wv1.w);
        float4 av0 = *reinterpret_cast<const float4*>(&As[k][tm]);
        float4 av1 = *reinterpret_cast<const float4*>(&As[k][tm+4]);
        unsigned long long a2[8];
        a2[0]=pack2(av0.x,av0.x); a2[1]=pack2(av0.y,av0.y);
        a2[2]=pack2(av0.z,av0.z); a2[3]=pack2(av0.w,av0.w);
        a2[4]=pack2(av1.x,av1.x); a2[5]=pack2(av1.y,av1.y);
        a2[6]=pack2(av1.z,av1.z); a2[7]=pack2(av1.w,av1.w);
#pragma unroll
        for (int i = 0; i < 8; i++)
#pragma unroll
            for (int jp = 0; jp < 4; jp++)
                ffma2(acc2[i][jp], a2[i], w2[jp]);
    }
}

// ---------------- generic fp32 tiled GEMM (FROZEN) ----------------------------
template<bool RELU>
__global__ void __launch_bounds__(256) gemm_kernel(
    const float* __restrict__ A, const float* __restrict__ W,
    const float* __restrict__ bias, float* __restrict__ C,
    int M, int K, int Nc)
{
    __shared__ float As[2][16][132];
    __shared__ float Ws[2][16][128];
    int bm = blockIdx.y * 128, bn = blockIdx.x * 128;
    int tid = threadIdx.x;
    int tm = (tid / 16) * 8, tn = (tid % 16) * 8;
    int m0 = tid >> 2, k4 = tid & 3;
    int wk = tid >> 5, wn = tid & 31;

    unsigned long long acc2[8][4];
#pragma unroll
    for (int i = 0; i < 8; i++)
#pragma unroll
        for (int jp = 0; jp < 4; jp++) acc2[i][jp] = 0ull;

    {
        float4 v0 = *reinterpret_cast<const float4*>(A + (size_t)(bm+m0)*K + k4*4);
        float4 v1 = *reinterpret_cast<const float4*>(A + (size_t)(bm+m0+64)*K + k4*4);
        As[0][k4*4+0][m0] = v0.x; As[0][k4*4+1][m0] = v0.y;
        As[0][k4*4+2][m0] = v0.z; As[0][k4*4+3][m0] = v0.w;
        As[0][k4*4+0][m0+64] = v1.x; As[0][k4*4+1][m0+64] = v1.y;
        As[0][k4*4+2][m0+64] = v1.z; As[0][k4*4+3][m0+64] = v1.w;
        cp_async16(&Ws[0][wk][wn*4],   W + (size_t)wk*Nc + bn + wn*4);
        cp_async16(&Ws[0][wk+8][wn*4], W + (size_t)(wk+8)*Nc + bn + wn*4);
        CP_ASYNC_COMMIT(); CP_ASYNC_WAIT_ALL();
    }
    __syncthreads();

    int nsteps = K >> 4;
    for (int s = 0; s < nsteps; s++) {
        int cur = s & 1, nxt = cur ^ 1;
        bool pre = (s + 1 < nsteps);
        float4 p0, p1;
        if (pre) {
            int k0n = (s + 1) << 4;
            p0 = *reinterpret_cast<const float4*>(A + (size_t)(bm+m0)*K + k0n + k4*4);
            p1 = *reinterpret_cast<const float4*>(A + (size_t)(bm+m0+64)*K + k0n + k4*4);
            cp_async16(&Ws[nxt][wk][wn*4],   W + (size_t)(k0n+wk)*Nc + bn + wn*4);
            cp_async16(&Ws[nxt][wk+8][wn*4], W + (size_t)(k0n+wk+8)*Nc + bn + wn*4);
            CP_ASYNC_COMMIT();
        }
        gemm_tile_compute(As[cur], Ws[cur], tm, tn, acc2);
        if (pre) {
            As[nxt][k4*4+0][m0] = p0.x; As[nxt][k4*4+1][m0] = p0.y;
            As[nxt][k4*4+2][m0] = p0.z; As[nxt][k4*4+3][m0] = p0.w;
            As[nxt][k4*4+0][m0+64] = p1.x; As[nxt][k4*4+1][m0+64] = p1.y;
            As[nxt][k4*4+2][m0+64] = p1.z; As[nxt][k4*4+3][m0+64] = p1.w;
            CP_ASYNC_WAIT_ALL();
        }
        __syncthreads();
    }
#pragma unroll
    for (int i = 0; i < 8; i++)
#pragma unroll
        for (int jp = 0; jp < 4; jp++) {
            float lo, hi;
            unpack2(acc2[i][jp], lo, hi);
            float v0 = lo + bias[bn+tn+2*jp];
            float v1 = hi + bias[bn+tn+2*jp+1];
            if (RELU) { v0 = fmaxf(v0, 0.f); v1 = fmaxf(v1, 0.f); }
            float2 st; st.x = v0; st.y = v1;
            *reinterpret_cast<float2*>(&C[(size_t)(bm+tm+i)*Nc + bn+tn+2*jp]) = st;
        }
}

// ---------------- fused dual-QKV GEMM (FROZEN) --------------------------------
__global__ void __launch_bounds__(256) gemm_qkv2_kernel(
    const float* __restrict__ A,
    const float* __restrict__ Wl, const float* __restrict__ bl,
    const float* __restrict__ Wg, const float* __restrict__ bg,
    float* __restrict__ Cl, float* __restrict__ Cg,
    int M, int K)
{
    __shared__ float As[2][16][132];
    __shared__ float Ws[2][16][128];
    int bm = blockIdx.y * 128;
    int bnRaw = blockIdx.x * 128;
    bool isL = bnRaw < QKVD;
    const float* W    = isL ? Wl : Wg;
    const float* bias = isL ? bl : bg;
    float*       C    = isL ? Cl : Cg;
    int bn = isL ? bnRaw : bnRaw - QKVD;
    const int Nc = QKVD;
    int tid = threadIdx.x;
    int tm = (tid / 16) * 8, tn = (tid % 16) * 8;
    int m0 = tid >> 2, k4 = tid & 3;
    int wk = tid >> 5, wn = tid & 31;

    unsigned long long acc2[8][4];
#pragma unroll
    for (int i = 0; i < 8; i++)
#pragma unroll
        for (int jp = 0; jp < 4; jp++) acc2[i][jp] = 0ull;

    {
        float4 v0 = *reinterpret_cast<const float4*>(A + (size_t)(bm+m0)*K + k4*4);
        float4 v1 = *reinterpret_cast<const float4*>(A + (size_t)(bm+m0+64)*K + k4*4);
        As[0][k4*4+0][m0] = v0.x; As[0][k4*4+1][m0] = v0.y;
        As[0][k4*4+2][m0] = v0.z; As[0][k4*4+3][m0] = v0.w;
        As[0][k4*4+0][m0+64] = v1.x; As[0][k4*4+1][m0+64] = v1.y;
        As[0][k4*4+2][m0+64] = v1.z; As[0][k4*4+3][m0+64] = v1.w;
        cp_async16(&Ws[0][wk][wn*4],   W + (size_t)wk*Nc + bn + wn*4);
        cp_async16(&Ws[0][wk+8][wn*4], W + (size_t)(wk+8)*Nc + bn + wn*4);
        CP_ASYNC_COMMIT(); CP_ASYNC_WAIT_ALL();
    }
    __syncthreads();

    int nsteps = K >> 4;
    for (int s = 0; s < nsteps; s++) {
        int cur = s & 1, nxt = cur ^ 1;
        bool pre = (s + 1 < nsteps);
        float4 p0, p1;
        if (pre) {
            int k0n = (s + 1) << 4;
            p0 = *reinterpret_cast<const float4*>(A + (size_t)(bm+m0)*K + k0n + k4*4);
            p1 = *reinterpret_cast<const float4*>(A + (size_t)(bm+m0+64)*K + k0n + k4*4);
            cp_async16(&Ws[nxt][wk][wn*4],   W + (size_t)(k0n+wk)*Nc + bn + wn*4);
            cp_async16(&Ws[nxt][wk+8][wn*4], W + (size_t)(k0n+wk+8)*Nc + bn + wn*4);
            CP_ASYNC_COMMIT();
        }
        gemm_tile_compute(As[cur], Ws[cur], tm, tn, acc2);
        if (pre) {
            As[nxt][k4*4+0][m0] = p0.x; As[nxt][k4*4+1][m0] = p0.y;
            As[nxt][k4*4+2][m0] = p0.z; As[nxt][k4*4+3][m0] = p0.w;
            As[nxt][k4*4+0][m0+64] = p1.x; As[nxt][k4*4+1][m0+64] = p1.y;
            As[nxt][k4*4+2][m0+64] = p1.z; As[nxt][k4*4+3][m0+64] = p1.w;
            CP_ASYNC_WAIT_ALL();
        }
        __syncthreads();
    }
#pragma unroll
    for (int i = 0; i < 8; i++)
#pragma unroll
        for (int jp = 0; jp < 4; jp++) {
            float lo, hi;
            unpack2(acc2[i][jp], lo, hi);
            float2 st;
            st.x = lo + bias[bn+tn+2*jp];
            st.y = hi + bias[bn+tn+2*jp+1];
            *reinterpret_cast<float2*>(&C[(size_t)(bm+tm+i)*Nc + bn+tn+2*jp]) = st;
        }
}

// ---------------- split projection-1 GEMM (FROZEN) ----------------------------
template<int PHASE>
__global__ void __launch_bounds__(256) gemm_proj1_kernel(
    const float* __restrict__ A, int lda,
    const float* __restrict__ W,
    const float* __restrict__ bias,
    float* __restrict__ C,
    int M, int K, int Nc)
{
    __shared__ float As[2][16][132];
    __shared__ float Ws[2][16][128];
    int bm = blockIdx.y * 128, bn = blockIdx.x * 128;
    int tid = threadIdx.x;
    int tm = (tid / 16) * 8, tn = (tid % 16) * 8;
    int m0 = tid >> 2, k4 = tid & 3;
    int wk = tid >> 5, wn = tid & 31;

    unsigned long long acc2[8][4];
#pragma unroll
    for (int i = 0; i < 8; i++)
#pragma unroll
        for (int jp = 0; jp < 4; jp++) acc2[i][jp] = 0ull;

    {
        float4 v0 = *reinterpret_cast<const float4*>(A + (size_t)(bm+m0)*lda + k4*4);
        float4 v1 = *reinterpret_cast<const float4*>(A + (size_t)(bm+m0+64)*lda + k4*4);
        As[0][k4*4+0][m0] = v0.x; As[0][k4*4+1][m0] = v0.y;
        As[0][k4*4+2][m0] = v0.z; As[0][k4*4+3][m0] = v0.w;
        As[0][k4*4+0][m0+64] = v1.x; As[0][k4*4+1][m0+64] = v1.y;
        As[0][k4*4+2][m0+64] = v1.z; As[0][k4*4+3][m0+64] = v1.w;
        cp_async16(&Ws[0][wk][wn*4],   W + (size_t)wk*Nc + bn + wn*4);
        cp_async16(&Ws[0][wk+8][wn*4], W + (size_t)(wk+8)*Nc + bn + wn*4);
        CP_ASYNC_COMMIT(); CP_ASYNC_WAIT_ALL();
    }
    __syncthreads();

    int nsteps = K >> 4;
    for (int s = 0; s < nsteps; s++) {
        int cur = s & 1, nxt = cur ^ 1;
        bool pre = (s + 1 < nsteps);
        float4 p0, p1;
        if (pre) {
            int k0n = (s + 1) << 4;
            p0 = *reinterpret_cast<const float4*>(A + (size_t)(bm+m0)*lda + k0n + k4*4);
            p1 = *reinterpret_cast<const float4*>(A + (size_t)(bm+m0+64)*lda + k0n + k4*4);
            cp_async16(&Ws[nxt][wk][wn*4],   W + (size_t)(k0n+wk)*Nc + bn + wn*4);
            cp_async16(&Ws[nxt][wk+8][wn*4], W + (size_t)(k0n+wk+8)*Nc + bn + wn*4);
            CP_ASYNC_COMMIT();
        }
        gemm_tile_compute(As[cur], Ws[cur], tm, tn, acc2);
        if (pre) {
            As[nxt][k4*4+0][m0] = p0.x; As[nxt][k4*4+1][m0] = p0.y;
            As[nxt][k4*4+2][m0] = p0.z; As[nxt][k4*4+3][m0] = p0.w;
            As[nxt][k4*4+0][m0+64] = p1.x; As[nxt][k4*4+1][m0+64] = p1.y;
            As[nxt][k4*4+2][m0+64] = p1.z; As[nxt][k4*4+3][m0+64] = p1.w;
            CP_ASYNC_WAIT_ALL();
        }
        __syncthreads();
    }
#pragma unroll
    for (int i = 0; i < 8; i++)
#pragma unroll
        for (int jp = 0; jp < 4; jp++) {
            float lo, hi;
            unpack2(acc2[i][jp], lo, hi);
            float* cp = &C[(size_t)(bm+tm+i)*Nc + bn+tn+2*jp];
            if (PHASE == 0) {
                float2 st;
                st.x = lo + bias[bn+tn+2*jp];
                st.y = hi + bias[bn+tn+2*jp+1];
                *reinterpret_cast<float2*>(cp) = st;
            } else {
                float2 prev = *reinterpret_cast<const float2*>(cp);
                float2 st;
                st.x = fmaxf(prev.x + lo, 0.f);
                st.y = fmaxf(prev.y + hi, 0.f);
                *reinterpret_cast<float2*>(cp) = st;
            }
        }
}

// ---------------- PE GEMM (FROZEN) --------------------------------------------
__global__ void __launch_bounds__(256) gemm_pe_kernel(
    const float* __restrict__ xyzp,
    const float* __restrict__ nbr, int nbr_rows,
    const int* __restrict__ nidx,
    const float* __restrict__ w1, const float* __restrict__ b1,
    const float* __restrict__ w2, const float* __restrict__ b2,
    float* __restrict__ pos)
{
    __shared__ float As[2][16][132];
    __shared__ float Ws[2][16][128];
    __shared__ float xd[128][5];
    __shared__ float w1s[4][128];
    __shared__ float b1s[128];

    int bm = blockIdx.x * 128;
    int tid = threadIdx.x;
    int wk = tid >> 5, wn = tid & 31;

    for (int t = tid; t < 512; t += 256) w1s[t >> 7][t & 127] = w1[t];
    if (tid < 128) b1s[tid] = b1[tid];
    if (tid < 128) {
        int r  = bm + tid;
        int pi = r >> 4;
        int j  = r & 15;
        int b  = pi / NN;
        int id = nidx[(size_t)pi*KNN + j];
        const float* qp = xyzp + (size_t)pi * 4;
        const float* np = nbr + ((size_t)b * nbr_rows + id) * 4;
        xd[tid][0] = qp[0]-np[0]; xd[tid][1] = qp[1]-np[1];
        xd[tid][2] = qp[2]-np[2]; xd[tid][3] = qp[3]-np[3];
    }
    __syncthreads();

    int tm = (tid / 16) * 8, tn = (tid % 16) * 8;
    unsigned long long acc2[8][4];
#pragma unroll
    for (int i = 0; i < 8; i++)
#pragma unroll
        for (int jp = 0; jp < 4; jp++) acc2[i][jp] = 0ull;

#pragma unroll
    for (int t = tid; t < 2048; t += 256) {
        int m = t & 127, k = t >> 7;
        int kk = k;
        float hv = b1s[kk] + xd[m][0]*w1s[0][kk] + xd[m][1]*w1s[1][kk]
                           + xd[m][2]*w1s[2][kk] + xd[m][3]*w1s[3][kk];
        As[0][k][m] = fmaxf(hv, 0.f);
    }
    cp_async16(&Ws[0][wk][wn*4],   w2 + (size_t)wk*128 + wn*4);
    cp_async16(&Ws[0][wk+8][wn*4], w2 + (size_t)(wk+8)*128 + wn*4);
    CP_ASYNC_COMMIT(); CP_ASYNC_WAIT_ALL();
    __syncthreads();

    for (int s = 0; s < 8; s++) {
        int cur = s & 1, nxt = cur ^ 1;
        bool pre = (s + 1 < 8);
        if (pre) {
            int k0n = (s + 1) << 4;
            cp_async16(&Ws[nxt][wk][wn*4],   w2 + (size_t)(k0n+wk)*128 + wn*4);
            cp_async16(&Ws[nxt][wk+8][wn*4], w2 + (size_t)(k0n+wk+8)*128 + wn*4);
            CP_ASYNC_COMMIT();
#pragma unroll
            for (int t = tid; t < 2048; t += 256) {
                int m = t & 127, k = t >> 7;
                int kk = k0n + k;
                float hv = b1s[kk] + xd[m][0]*w1s[0][kk] + xd[m][1]*w1s[1][kk]
                                   + xd[m][2]*w1s[2][kk] + xd[m][3]*w1s[3][kk];
                As[nxt][k][m] = fmaxf(hv, 0.f);
            }
        }
        gemm_tile_compute(As[cur], Ws[cur], tm, tn, acc2);
        if (pre) CP_ASYNC_WAIT_ALL();
        __syncthreads();
    }
#pragma unroll
    for (int i = 0; i < 8; i++)
#pragma unroll
        for (int jp = 0; jp < 4; jp++) {
            float lo, hi;
            unpack2(acc2[i][jp], lo, hi);
            float2 st;
            st.x = lo + b2[tn+2*jp];
            st.y = hi + b2[tn+2*jp+1];
            *reinterpret_cast<float2*>(&pos[(size_t)(bm+tm+i)*128 + tn+2*jp]) = st;
        }
}

// ---------------- kvmax (FROZEN) ----------------------------------------------
__global__ void __launch_bounds__(128) kvmax_kernel()
{
    int b = blockIdx.y, r = blockIdx.x, c = threadIdx.x;
    int src = d_down_idx[b*NDWN + r];
    const int* pidx = d_idx_l + ((size_t)b*NN + src)*KNN;
    float km = -3.4e38f, vm = -3.4e38f;
#pragma unroll
    for (int j = 0; j < KNN; j++) {
        int id = pidx[j];
        const float* row = d_qkv_g + ((size_t)b*NN + id)*QKVD;
        km = fmaxf(km, row[AD   + c]);
        vm = fmaxf(vm, row[2*AD + c]);
    }
    d_kmax[((size_t)b*NDWN + r)*AD + c] = km;
    d_vmax[((size_t)b*NDWN + r)*AD + c] = vm;
}

// ---------------- attention: 2 barriers/point (arithmetic unchanged) ----------
// All 8 points' neighbor indices loaded up front (one coalesced 128-int read).
// Per point: sync after ts writes, sync after m_s writes; next point's ts
// overwrite is fenced by the m_s sync (stats readers finished before it).
__global__ void __launch_bounds__(128) attn_kernel(
    const int*  __restrict__ nidx,
    const float* __restrict__ qsrc,  int qstride,
    const float* __restrict__ kbase, const float* __restrict__ vbase,
    int kv_stride, int kv_rows,
    const float* __restrict__ pos,
    const float* __restrict__ fg,  const float* __restrict__ fb,
    float* __restrict__ out, int out_coloff)
{
    __shared__ float ts[KNN*128];
    __shared__ int   sidx_all[PPB*KNN];     // 128
    __shared__ float m_s[KNN], i_s[KNN];

    int b = blockIdx.y;
    int c = threadIdx.x;
    int lane = c & 31, warp = c >> 5;
    float gr = fg[c], br = fb[c];
    const float inv_scale = 0.08838834764831845f;

    sidx_all[c] = nidx[((size_t)b * NN + blockIdx.x * PPB) * KNN + c];
    __syncthreads();

    for (int pp = 0; pp < PPB; pp++) {
        int i = blockIdx.x * PPB + pp;
        size_t bi = (size_t)b * NN + i;
        const int* sidx = sidx_all + pp*KNN;

        float qv = qsrc[bi*qstride + c];
        const float* prow = pos + bi * (KNN*128) + c;
        float tr[KNN], vp[KNN];
#pragma unroll
        for (int j = 0; j < KNN; j++) {
            size_t kr = ((size_t)b*kv_rows + sidx[j]) * kv_stride;
            float pv = prow[j*128];
            tr[j] = qv - kbase[kr + c] + pv;
            vp[j] = vbase[kr + c] + pv;
            ts[j*128 + c] = tr[j];
        }
        __syncthreads();

#pragma unroll
        for (int jj = 0; jj < 4; jj++) {
            int j = warp*4 + jj;
            float v0 = ts[j*128+lane],    v1 = ts[j*128+lane+32];
            float v2 = ts[j*128+lane+64], v3 = ts[j*128+lane+96];
            float s  = v0+v1+v2+v3;
            float ss = v0*v0+v1*v1+v2*v2+v3*v3;
#pragma unroll
            for (int off = 16; off; off >>= 1) {
                s  += __shfl_xor_sync(0xffffffffu, s,  off);
                ss += __shfl_xor_sync(0xffffffffu, ss, off);
            }
            if (lane == 0) {
                float m   = s * (1.f/128.f);
                float var = ss * (1.f/128.f) - m*m;
                if (var < 0.f) var = 0.f;
                m_s[j] = m;
                i_s[j] = 1.f / sqrtf(var + 1e-5f);
            }
        }
        __syncthreads();

        float a[KNN], mx = -3.4e38f;
#pragma unroll
        for (int j = 0; j < KNN; j++) {
            a[j] = ((tr[j] - m_s[j]) * i_s[j] * gr + br) * inv_scale;
            mx = fmaxf(mx, a[j]);
        }
        float se = 0.f, ov = 0.f;
#pragma unroll
        for (int j = 0; j < KNN; j++) {
            float e = expf(a[j] - mx);
            se += e;
            ov += e * vp[j];
        }
        out[bi*(2*AD) + out_coloff + c] = ov / se;
        // no trailing sync: next point's ts writes are ordered by the m_s sync
        // (all stats-phase ts reads complete before it); m_s reads here finish
        // before this thread reaches the next point's first sync.
    }
}

// ---------------- launcher ----------------------------------------------------
extern "C" void kernel_launch(void* const* d_in, const int* in_sizes, int n_in,
                              void* d_out, int out_size)
{
    const float* xyzp     = (const float*)d_in[0];
    const float* features = (const float*)d_in[1];
    const float* l_qkv_w  = (const float*)d_in[2];
    const float* l_qkv_b  = (const float*)d_in[3];
    const float* l_pe_w1  = (const float*)d_in[4];
    const float* l_pe_b1  = (const float*)d_in[5];
    const float* l_pe_w2  = (const float*)d_in[6];
    const float* l_pe_b2  = (const float*)d_in[7];
    const float* l_fc_g   = (const float*)d_in[8];
    const float* l_fc_b   = (const float*)d_in[9];
    const float* g_qkv_w  = (const float*)d_in[10];
    const float* g_qkv_b  = (const float*)d_in[11];
    const float* g_pe_w1  = (const float*)d_in[12];
    const float* g_pe_b1  = (const float*)d_in[13];
    const float* g_pe_w2  = (const float*)d_in[14];
    const float* g_pe_b2  = (const float*)d_in[15];
    const float* g_fc_g   = (const float*)d_in[16];
    const float* g_fc_b   = (const float*)d_in[17];
    const float* proj_w1  = (const float*)d_in[18];
    const float* proj_b1  = (const float*)d_in[19];
    const float* proj_w2  = (const float*)d_in[20];
    const float* proj_b2  = (const float*)d_in[21];
    float* out = (float*)d_out;

    float *qkv_l, *qkv_g, *cat_p, *hid_p, *kmax_p, *vmax_p, *dxyzp_p, *posl_p, *posg_p;
    int *idx_l, *idx_inv;
    cudaGetSymbolAddress((void**)&qkv_l,   d_qkv_l);
    cudaGetSymbolAddress((void**)&qkv_g,   d_qkv_g);
    cudaGetSymbolAddress((void**)&cat_p,   d_cat);
    cudaGetSymbolAddress((void**)&hid_p,   d_hid);
    cudaGetSymbolAddress((void**)&kmax_p,  d_kmax);
    cudaGetSymbolAddress((void**)&vmax_p,  d_vmax);
    cudaGetSymbolAddress((void**)&dxyzp_p, d_down_xyzp);
    cudaGetSymbolAddress((void**)&posl_p,  d_pos_l);
    cudaGetSymbolAddress((void**)&posg_p,  d_pos_g);
    cudaGetSymbolAddress((void**)&idx_l,   d_idx_l);
    cudaGetSymbolAddress((void**)&idx_inv, d_idx_inv);

    const int FPS_SMEM = 3 * NN * (int)sizeof(float);
    cudaFuncSetAttribute(fps_kernel, cudaFuncAttributeMaxDynamicSharedMemorySize, FPS_SMEM);

    static cudaStream_t sA = 0, sB = 0, sC = 0;
    static cudaEvent_t evRoot, evDown, evKNN, evQKV, evPl, evB, evC, evPh1b;
    static bool inited = false;
    if (!inited) {
        int leastP = 0, greatestP = 0;
        cudaDeviceGetStreamPriorityRange(&leastP, &greatestP);
        cudaStreamCreateWithPriority(&sA, cudaStreamNonBlocking, leastP);
        cudaStreamCreateWithPriority(&sB, cudaStreamNonBlocking, greatestP);
        cudaStreamCreateWithPriority(&sC, cudaStreamNonBlocking, greatestP);
        cudaEventCreateWithFlags(&evRoot, cudaEventDisableTiming);
        cudaEventCreateWithFlags(&evDown, cudaEventDisableTiming);
        cudaEventCreateWithFlags(&evKNN,  cudaEventDisableTiming);
        cudaEventCreateWithFlags(&evQKV,  cudaEventDisableTiming);
        cudaEventCreateWithFlags(&evPl,   cudaEventDisableTiming);
        cudaEventCreateWithFlags(&evB,    cudaEventDisableTiming);
        cudaEventCreateWithFlags(&evC,    cudaEventDisableTiming);
        cudaEventCreateWithFlags(&evPh1b, cudaEventDisableTiming);
        inited = true;
    }

    const int M = BB * NN;
    const int PE_BLOCKS = (BB*NN*KNN) / 128;   // 2048

    cudaEventRecord(evRoot, 0);
    cudaStreamWaitEvent(sA, evRoot, 0);
    cudaStreamWaitEvent(sB, evRoot, 0);

    // sA: self-KNN (split) -> PE-local
    knn_kernel<<<dim3(NN/128, BB), 256, 0, sA>>>(xyzp, NN, xyzp, NN, idx_l);
    cudaEventRecord(evKNN, sA);
    gemm_pe_kernel<<<PE_BLOCKS, 256, 0, sA>>>(xyzp, xyzp, NN, idx_l,
                                              l_pe_w1, l_pe_b1, l_pe_w2, l_pe_b2, posl_p);

    // sB: FPS -> gather (fork sC after down points ready)
    fps_kernel<<<BB, 1024, FPS_SMEM, sB>>>(xyzp);
    gather_down_kernel<<<(BB*NDWN + 255)/256, 256, 0, sB>>>(xyzp);
    cudaEventRecord(evDown, sB);
    cudaStreamWaitEvent(sC, evDown, 0);

    // sC: inv-KNN (split) -> PE-global
    knn_kernel<<<dim3(NN/128, BB), 256, 0, sC>>>(xyzp, NN, dxyzp_p, NDWN, idx_inv);
    gemm_pe_kernel<<<PE_BLOCKS, 256, 0, sC>>>(xyzp, dxyzp_p, NDWN, idx_inv,
                                              g_pe_w1, g_pe_b1, g_pe_w2, g_pe_b2, posg_p);

    // default: fused dual-QKV GEMM
    gemm_qkv2_kernel<<<dim3(2*QKVD/128, M/128), 256>>>(features,
                                                       l_qkv_w, l_qkv_b,
                                                       g_qkv_w, g_qkv_b,
                                                       qkv_l, qkv_g, M, DIMF);
    cudaEventRecord(evQKV, 0);

    // sA: local attention, then proj1 local half (full M)
    cudaStreamWaitEvent(sA, evQKV, 0);
    attn_kernel<<<dim3(NN/PPB, BB), 128, 0, sA>>>(idx_l, qkv_l, QKVD,
                                                  qkv_l + AD, qkv_l + 2*AD, QKVD, NN,
                                                  posl_p, l_fc_g, l_fc_b, cat_p, 0);
    gemm_proj1_kernel<0><<<dim3(DIMF/128, M/128), 256, 0, sA>>>(
        cat_p, 2*AD, proj_w1, proj_b1, hid_p, M, AD, DIMF);
    cudaEventRecord(evPl, sA);

    // sB: kvmax
    cudaStreamWaitEvent(sB, evKNN, 0);
    cudaStreamWaitEvent(sB, evQKV, 0);
    kvmax_kernel<<<dim3(NDWN, BB), 128, 0, sB>>>();
    cudaEventRecord(evB, sB);

    // sC: global attention (whole)
    cudaStreamWaitEvent(sC, evB, 0);
    attn_kernel<<<dim3(NN/PPB, BB), 128, 0, sC>>>(idx_inv, qkv_g, QKVD,
                                                  kmax_p, vmax_p, AD, NDWN,
                                                  posg_p, g_fc_g, g_fc_b, cat_p, AD);
    cudaEventRecord(evC, sC);

    // Tail, half-M pipelined:
    //   default: ph1(batch0) -> proj2(batch0) -> [wait ph1(batch1)] proj2(batch1)
    //   sA:      [wait evC]   ph1(batch1)   (overlaps proj2(batch0))
    cudaStreamWaitEvent(0, evPl, 0);
    cudaStreamWaitEvent(0, evC, 0);
    gemm_proj1_kernel<1><<<dim3(DIMF/128, NN/128), 256>>>(
        cat_p + AD, 2*AD, proj_w1 + (size_t)AD*DIMF, proj_b1, hid_p, NN, AD, DIMF);

    cudaStreamWaitEvent(sA, evC, 0);   // sA already ordered after evPl
    gemm_proj1_kernel<1><<<dim3(DIMF/128, NN/128), 256, 0, sA>>>(
        cat_p + (size_t)NN*2*AD + AD, 2*AD, proj_w1 + (size_t)AD*DIMF, proj_b1,
        hid_p + (size_t)NN*DIMF, NN, AD, DIMF);
    cudaEventRecord(evPh1b, sA);

    gemm_kernel<false><<<dim3(DIMF/128, NN/128), 256>>>(
        hid_p, proj_w2, proj_b2, out, NN, DIMF, DIMF);
    cudaStreamWaitEvent(0, evPh1b, 0);
    gemm_kernel<false><<<dim3(DIMF/128, NN/128), 256>>>(
        hid_p + (size_t)NN*DIMF, proj_w2, proj_b2, out + (size_t)NN*DIMF, NN, DIMF, DIMF);

    (void)in_sizes; (void)n_in; (void)out_size;
}